// round 14
// baseline (speedup 1.0000x reference)
#include <cuda_runtime.h>
#include <cuda_bf16.h>
#include <math.h>
#include <stdint.h>

#define Bb 32
#define Tt 64
#define Ee 512
#define Hh 1024
#define VTv 32000
#define HB (Hh*Bb)
#define G4 (4*Hh)
#define G4B (G4*Bb)
#define NBLK 128
#define NTHR 1024

typedef unsigned long long u64;
typedef __nv_bfloat16 bf16;

__device__ __forceinline__ float sigf(float x) { return 1.f/(1.f+expf(-x)); }
__device__ __forceinline__ uint32_t s2u(const void* p) {
    uint32_t a;
    asm("{ .reg .u64 t; cvta.to.shared.u64 t, %1; cvt.u32.u64 %0, t; }" : "=r"(a) : "l"(p));
    return a;
}
__device__ __forceinline__ void mb_init(uint32_t m, uint32_t c) {
    asm volatile("mbarrier.init.shared.b64 [%0], %1;" :: "r"(m), "r"(c) : "memory");
}
__device__ __forceinline__ void mb_expect(uint32_t m, uint32_t b) {
    asm volatile("mbarrier.arrive.expect_tx.shared.b64 _, [%0], %1;" :: "r"(m), "r"(b) : "memory");
}
__device__ __forceinline__ void mb_wait(uint32_t m, int par) {
    uint32_t done;
    do {
        asm volatile(
            "{\n\t.reg .pred p;\n\t"
            "mbarrier.try_wait.parity.acquire.cta.shared::cta.b64 p, [%1], %2;\n\t"
            "selp.b32 %0,1,0,p;\n\t}"
            : "=r"(done) : "r"(m), "r"((uint32_t)par) : "memory");
    } while (!done);
}
__device__ __forceinline__ void bulk_g2s(uint32_t d, const void* s, uint32_t b, uint32_t m) {
    asm volatile(
        "cp.async.bulk.shared::cluster.global.mbarrier::complete_tx::bytes [%0], [%1], %2, [%3];"
        :: "r"(d), "l"(s), "r"(b), "r"(m) : "memory");
}
__device__ __forceinline__ void hmma(float* c, const uint32_t* a, const uint32_t* b) {
    asm volatile("mma.sync.aligned.m16n8k16.row.col.f32.bf16.bf16.f32 "
        "{%0,%1,%2,%3}, {%4,%5,%6,%7}, {%8,%9}, {%0,%1,%2,%3};"
        : "+f"(c[0]), "+f"(c[1]), "+f"(c[2]), "+f"(c[3])
        : "r"(a[0]), "r"(a[1]), "r"(a[2]), "r"(a[3]), "r"(b[0]), "r"(b[1]));
}
__device__ __forceinline__ void ldsm4(uint32_t* r, uint32_t a) {
    asm volatile("ldmatrix.sync.aligned.m8n8.x4.shared.b16 {%0,%1,%2,%3}, [%4];"
        : "=r"(r[0]), "=r"(r[1]), "=r"(r[2]), "=r"(r[3]) : "r"(a));
}
__device__ __forceinline__ void ldsm2(uint32_t* r, uint32_t a) {
    asm volatile("ldmatrix.sync.aligned.m8n8.x2.shared.b16 {%0,%1}, [%2];"
        : "=r"(r[0]), "=r"(r[1]) : "r"(a));
}

// padded-row layout: 72 halves (144B rows, 16B-aligned for ldmatrix)
#define ACH 9216
#define ACHB 18432
#define BCH 2304
#define BCHB 4608
#define XTC 36864

// ---------------- device globals ----------------
__device__ __align__(16) float g_encHs[Tt*HB];
__device__ __align__(16) float g_h1d[2*HB];
__device__ __align__(16) float g_c0e[HB];
__device__ __align__(16) float g_c1e[HB];
__device__ __align__(16) float g_c0d[HB];
__device__ __align__(16) float g_c1d[HB];
__device__ __align__(16) float g_scoresT[Tt*Bb];
__device__ __align__(16) float g_bre[2*G4];
__device__ __align__(16) float g_brd[2*G4];
__device__ __align__(16) float g_zxe[Tt*G4B];
__device__ __align__(16) float g_zxd[Tt*G4B];
__device__ __align__(16) float g_wcP[4*Hh*Bb];
__device__ __align__(16) float g_oeP[4*Ee*Bb];
__device__ __align__(16) float g_elog[(size_t)Tt*Bb*VTv];
__device__ __align__(16) bf16 g_AxeH[32*16*ACH]; __device__ __align__(16) bf16 g_AxeL[32*16*ACH];
__device__ __align__(16) bf16 g_Ae0H[32*16*ACH]; __device__ __align__(16) bf16 g_Ae0L[32*16*ACH];
__device__ __align__(16) bf16 g_Ae1H[32*32*ACH]; __device__ __align__(16) bf16 g_Ae1L[32*32*ACH];
__device__ __align__(16) bf16 g_AxdH[32*16*ACH]; __device__ __align__(16) bf16 g_AxdL[32*16*ACH];
__device__ __align__(16) bf16 g_Ad0H[32*16*ACH]; __device__ __align__(16) bf16 g_Ad0L[32*16*ACH];
__device__ __align__(16) bf16 g_Ad1H[32*32*ACH]; __device__ __align__(16) bf16 g_Ad1L[32*32*ACH];
__device__ __align__(16) bf16 g_AwcH[8*32*ACH];  __device__ __align__(16) bf16 g_AwcL[8*32*ACH];
__device__ __align__(16) bf16 g_ApjH[4*16*ACH];  __device__ __align__(16) bf16 g_ApjL[4*16*ACH];
__device__ __align__(16) bf16 g_XsH[64*XTC]; __device__ __align__(16) bf16 g_XsL[64*XTC];
__device__ __align__(16) bf16 g_XtH[64*XTC]; __device__ __align__(16) bf16 g_XtL[64*XTC];
__device__ __align__(16) bf16 g_txH[64*XTC]; __device__ __align__(16) bf16 g_txL[64*XTC];
__device__ __align__(16) bf16 g_h0eH[2*XTC]; __device__ __align__(16) bf16 g_h0eL[2*XTC];
__device__ __align__(16) bf16 g_encSH[2*XTC];__device__ __align__(16) bf16 g_encSL[2*XTC];
__device__ __align__(16) bf16 g_h1SH[2*XTC]; __device__ __align__(16) bf16 g_h1SL[2*XTC];
__device__ __align__(16) bf16 g_ctxH[XTC];   __device__ __align__(16) bf16 g_ctxL[XTC];
__device__ __align__(16) bf16 g_htH[XTC];    __device__ __align__(16) bf16 g_htL[XTC];
__device__ __align__(16) bf16 g_zeroX[XTC];
__device__ __align__(16) bf16 g_oeH[2048*Ee]; __device__ __align__(16) bf16 g_oeL[2048*Ee];
__device__ __align__(16) bf16 g_WoTH[(long)VTv*Ee]; __device__ __align__(16) bf16 g_WoTL[(long)VTv*Ee];
__device__ unsigned g_bar;

#define SLOT_SZ 46080
#define RED_OFF 184320
#define ATT_OFF 218112
#define MBF_OFF 226560
#define SMEM_SEQ 226592

__device__ __forceinline__ void stX(bf16* XH, bf16* XL, int b, int k, float v) {
    bf16 h = __float2bfloat16_rn(v);
    bf16 l = __float2bfloat16_rn(v - __bfloat162float(h));
    int off = ((k >> 6)*32 + b)*72 + (k & 63);
    XH[off] = h; XL[off] = l;
}
__device__ __forceinline__ void splitw(float w, bf16* H, bf16* L, long i) {
    bf16 a = __float2bfloat16_rn(w);
    H[i] = a; L[i] = __float2bfloat16_rn(w - __bfloat162float(a));
}

// ---------------- prep ----------------
__global__ void prep(const float* __restrict__ encW, const float* __restrict__ encb,
                     const float* __restrict__ decW, const float* __restrict__ decb,
                     const float* __restrict__ Wc,   const float* __restrict__ pW) {
    int sec = blockIdx.y;
    long t0 = (long)blockIdx.x*blockDim.x + threadIdx.x;
    long stride = (long)gridDim.x*blockDim.x;
    if (sec < 2) {
        const float* W = sec ? decW : encW;
        bf16 *xh = sec ? g_AxdH : g_AxeH, *xl = sec ? g_AxdL : g_AxeL;
        bf16 *h0h = sec ? g_Ad0H : g_Ae0H, *h0l = sec ? g_Ad0L : g_Ae0L;
        bf16 *l1h = sec ? g_Ad1H : g_Ae1H, *l1l = sec ? g_Ad1L : g_Ae1L;
        for (long q = t0; q < 32L*16*128*64; q += stride) {
            int kl = (int)(q & 63), m = (int)((q>>6)&127);
            int ch = (int)((q>>13)&15), ct = (int)(q>>17);
            long idx = (long)(ct*16 + ch)*ACH + m*72 + kl;
            int col = ct*128 + m;
            long cofs = (long)(col & 3)*1024 + (col >> 2);
            splitw(W[(long)(ch*64 + kl)*4096 + cofs], xh, xl, idx);
            splitw(W[(long)(1024 + ch*64 + kl)*4096 + cofs], h0h, h0l, idx);
        }
        for (long q = t0; q < 32L*32*128*64; q += stride) {
            int kl = (int)(q & 63), m = (int)((q>>6)&127);
            int ch = (int)((q>>13)&31), ct = (int)(q>>18);
            long idx = (long)(ct*32 + ch)*ACH + m*72 + kl;
            int col = ct*128 + m;
            splitw(W[(long)(2048 + ch*64 + kl)*4096 + (long)(col&3)*1024 + (col>>2)],
                   l1h, l1l, idx);
        }
    } else if (sec == 2) {
        for (long q = t0; q < 8L*32*128*64; q += stride) {
            int kl = (int)(q & 63), m = (int)((q>>6)&127);
            int ch = (int)((q>>13)&31), ct = (int)(q>>18);
            long idx = (long)(ct*32 + ch)*ACH + m*72 + kl;
            splitw(Wc[(long)(ch*64 + kl)*1024 + ct*128 + m], g_AwcH, g_AwcL, idx);
        }
        for (long q = t0; q < 4L*16*128*64; q += stride) {
            int kl = (int)(q & 63), m = (int)((q>>6)&127);
            int ch = (int)((q>>13)&15), ct = (int)(q>>17);
            long idx = (long)(ct*16 + ch)*ACH + m*72 + kl;
            splitw(pW[(long)(ch*64 + kl)*512 + ct*128 + m], g_ApjH, g_ApjL, idx);
        }
    } else {
        for (long i = t0; i < 2*G4; i += stride) {
            int l = (int)(i >> 12), col = (int)(i & 4095), n = col>>2, g = col&3;
            g_bre[i] = encb[(l<<12) + g*Hh + n];
            g_brd[i] = decb[(l<<12) + g*Hh + n];
        }
        for (long i = t0; i < HB; i += stride) {
            g_c0e[i]=0.f; g_c1e[i]=0.f; g_c0d[i]=0.f; g_c1d[i]=0.f;
            g_h1d[i]=0.f; g_h1d[i+HB]=0.f;
        }
        bf16 z = __float2bfloat16_rn(0.f);
        for (long i = t0; i < XTC; i += stride) {
            g_zeroX[i] = z;
            g_h1SH[i]=z; g_h1SH[i+XTC]=z; g_h1SL[i]=z; g_h1SL[i+XTC]=z;
        }
        if (t0 == 0) g_bar = 0u;
    }
}

// tiled transpose: proj_Wo[512][32000] -> WoT[32000][512] bf16 hi/lo
__global__ void transWo(const float* __restrict__ Wo) {
    __shared__ float tile[32][33];
    int n0 = blockIdx.x*32, k0 = blockIdx.y*32;
    int tx = threadIdx.x, ty = threadIdx.y;
    #pragma unroll
    for (int i = 0; i < 4; i++)
        tile[ty + i*8][tx] = Wo[(long)(k0 + ty + i*8)*VTv + n0 + tx];
    __syncthreads();
    #pragma unroll
    for (int i = 0; i < 4; i++) {
        float w = tile[tx][ty + i*8];
        splitw(w, g_WoTH, g_WoTL, (long)(n0 + ty + i*8)*Ee + k0 + tx);
    }
}

// ---------------- embedding + input projection -> XT ----------------
__global__ void embed2(const int* __restrict__ src, const int* __restrict__ tgt,
                       const float* __restrict__ s_emb, const float* __restrict__ t_emb,
                       const float4* __restrict__ sW, const float4* __restrict__ sB,
                       const float4* __restrict__ tW, const float4* __restrict__ tB) {
    int z = blockIdx.z;
    const int* tok = z ? tgt : src;
    const float* emb = z ? t_emb : s_emb;
    const float4* W4 = z ? tW : sW;
    const float4* b4 = z ? tB : sB;
    bf16* XH = (z ? g_XtH : g_XsH);
    bf16* XL = (z ? g_XtL : g_XsL);
    int t = blockIdx.y;
    int w = threadIdx.x >> 5, lane = threadIdx.x & 31;
    int n4 = blockIdx.x * 8 + w;
    const float* ar = emb + (long)tok[lane*Tt + t] * Ee;
    float4 acc = b4[n4];
    #pragma unroll 4
    for (int k = 0; k < Ee; k++) {
        float a = ar[k];
        float4 wv = W4[k*(Hh/4) + n4];
        acc.x += a*wv.x; acc.y += a*wv.y; acc.z += a*wv.z; acc.w += a*wv.w;
    }
    bf16* xh = XH + (long)t*XTC;
    bf16* xl = XL + (long)t*XTC;
    stX(xh, xl, lane, n4*4+0, acc.x);
    stX(xh, xl, lane, n4*4+1, acc.y);
    stX(xh, xl, lane, n4*4+2, acc.z);
    stX(xh, xl, lane, n4*4+3, acc.w);
}

// ---------------- HMMA staged GEMM (1024 thr: 4m x 4n x 2k warps) ------------
struct Pipe { uint32_t ph; unsigned base; };

__device__ void stage_mma(Pipe& P, char* sm, uint32_t smb,
    const char* Ah, const char* Al,
    const char* B1h, const char* B1l, const char* B2h, const char* B2l,
    int nch1, int nch, float* red)
{
    int tid = threadIdx.x, lane = tid & 31, wid = tid >> 5;
    int wm = wid >> 3, wn = (wid >> 1) & 3, wk = wid & 1;
    int gr = lane >> 2, tig = lane & 3;
    uint32_t aoff = (uint32_t)((lane & 15)*144 + ((lane >> 4) << 4));
    uint32_t boff = (uint32_t)((lane & 7)*144 + (((lane >> 3) & 1) << 4));
    float acc[2][4] = {};
    int issued = 0;
    for (int it = 0; it < nch; it++) {
        if (tid == 0) {
            for (; issued < nch && issued <= it + 3; issued++) {
                int sl = (int)((P.base + issued) & 3);
                uint32_t fb = smb + MBF_OFF + sl*8;
                mb_expect(fb, SLOT_SZ);
                uint32_t d = smb + sl*SLOT_SZ;
                bulk_g2s(d,          Ah + (long)issued*ACHB, ACHB, fb);
                bulk_g2s(d + ACHB,   Al + (long)issued*ACHB, ACHB, fb);
                const char* bh = (issued < nch1) ? B1h + (long)issued*BCHB : B2h + (long)(issued-nch1)*BCHB;
                const char* bl = (issued < nch1) ? B1l + (long)issued*BCHB : B2l + (long)(issued-nch1)*BCHB;
                bulk_g2s(d + 2*ACHB,        bh, BCHB, fb);
                bulk_g2s(d + 2*ACHB + BCHB, bl, BCHB, fb);
            }
        }
        int sl = (int)((P.base + it) & 3);
        mb_wait(smb + MBF_OFF + sl*8, (P.ph >> sl) & 1);
        P.ph ^= 1u << sl;
        uint32_t d = smb + sl*SLOT_SZ;
        uint32_t dAh = d, dAl = d + ACHB, dBh = d + 2*ACHB, dBl = d + 2*ACHB + BCHB;
        #pragma unroll
        for (int ks = 0; ks < 2; ks++) {
            uint32_t kadd = (uint32_t)((wk*32 + ks*16) << 1);
            uint32_t bh2[2], bl2[2];
            uint32_t bbase = (uint32_t)(wn*8*144) + kadd + boff;
            ldsm2(bh2, dBh + bbase);
            ldsm2(bl2, dBl + bbase);
            #pragma unroll
            for (int mt = 0; mt < 2; mt++) {
                uint32_t abase = (uint32_t)((wm*32 + mt*16)*144) + kadd + aoff;
                uint32_t a4[4], a4l[4];
                ldsm4(a4,  dAh + abase);
                ldsm4(a4l, dAl + abase);
                hmma(acc[mt], a4,  bh2);
                hmma(acc[mt], a4l, bh2);
                hmma(acc[mt], a4,  bl2);
            }
        }
        __syncthreads();
    }
    P.base += nch;
    float* rw = red + wk*4224;
    #pragma unroll
    for (int mt = 0; mt < 2; mt++) {
        int r0 = wm*32 + mt*16 + gr;
        int cb = wn*8 + tig*2;
        rw[r0*33 + cb]     = acc[mt][0];
        rw[r0*33 + cb + 1] = acc[mt][1];
        rw[(r0+8)*33 + cb]     = acc[mt][2];
        rw[(r0+8)*33 + cb + 1] = acc[mt][3];
    }
    __syncthreads();
}

__device__ void lstm_fin(const float* red, int ct, const float* __restrict__ bias,
                         const float* __restrict__ zx, float* __restrict__ c,
                         float* __restrict__ hlin, bf16* XH, bf16* XL) {
    for (int i = threadIdx.x; i < 1024; i += NTHR) {
        int nl = i >> 5, b = i & 31;
        int col = ct*128 + nl*4;
        const float* r0 = red + (nl*4)*33 + b;
        const float* r1 = r0 + 4224;
        float zi = r0[0]  + r1[0]  + bias[col];
        float zj = r0[33] + r1[33] + bias[col+1];
        float zf = r0[66] + r1[66] + bias[col+2];
        float zo = r0[99] + r1[99] + bias[col+3];
        if (zx) {
            const float* z = zx + (long)col*32 + b;
            zi += z[0]; zj += z[32]; zf += z[64]; zo += z[96];
        }
        int idx = (ct*32 + nl)*32 + b;
        float cn = c[idx]*sigf(zf + 1.f) + sigf(zi)*tanhf(zj);
        c[idx] = cn;
        float h = tanhf(cn)*sigf(zo);
        if (hlin) hlin[idx] = h;
        stX(XH, XL, b, ct*32 + nl, h);
    }
    __syncthreads();
}

// ---------------- xgate (HMMA) ----------------
__global__ void __launch_bounds__(NTHR,1) xgate_mma() {
    extern __shared__ __align__(16) char dynsmem[];
    uint32_t smb = s2u(dynsmem);
    float* red = (float*)(dynsmem + RED_OFF);
    if (threadIdx.x == 0) {
        #pragma unroll
        for (int j = 0; j < 4; j++) mb_init(smb + MBF_OFF + j*8, 1);
        asm volatile("fence.proxy.async.shared::cta;" ::: "memory");
    }
    __syncthreads();
    Pipe P{0,0};
    int ct = blockIdx.x, t = blockIdx.y, z = blockIdx.z;
    const char* Ah = (const char*)((z ? g_AxdH : g_AxeH) + (long)ct*16*ACH);
    const char* Al = (const char*)((z ? g_AxdL : g_AxeL) + (long)ct*16*ACH);
    const char* Bh = (const char*)((z ? g_XtH : g_XsH) + (long)t*XTC);
    const char* Bl = (const char*)((z ? g_XtL : g_XsL) + (long)t*XTC);
    stage_mma(P, dynsmem, smb, Ah, Al, Bh, Bl, Bh, Bl, 16, 16, red);
    float* out = (z ? g_zxd : g_zxe) + (long)t*G4B;
    for (int i = threadIdx.x; i < 4096; i += NTHR) {
        int cl = i >> 5, b = i & 31;
        out[(long)(ct*128 + cl)*32 + b] = red[cl*33 + b] + red[4224 + cl*33 + b];
    }
}

// ---------------- grid barrier ----------------
__device__ __forceinline__ void gbar(unsigned &tgt) {
    tgt += NBLK;
    __syncthreads();
    if (threadIdx.x == 0) {
        __threadfence();
        atomicAdd(&g_bar, 1u);
        unsigned v;
        do {
            asm volatile("ld.acquire.gpu.u32 %0,[%1];" : "=r"(v) : "l"(&g_bar) : "memory");
        } while (v < tgt);
    }
    __syncthreads();
}

// ---------------- persistent sequence kernel ----------------
__global__ void __launch_bounds__(NTHR,1) seq_kernel(const float* __restrict__ b_c,
                                                     const float* __restrict__ proj_b) {
    extern __shared__ __align__(16) char dynsmem[];
    uint32_t smb = s2u(dynsmem);
    float* red = (float*)(dynsmem + RED_OFF);
    float* attw = (float*)(dynsmem + ATT_OFF);
    int tid = threadIdx.x, lane = tid & 31, wid = tid >> 5, bid = blockIdx.x;
    unsigned tgt = 0;
    if (tid == 0) {
        #pragma unroll
        for (int j = 0; j < 4; j++) mb_init(smb + MBF_OFF + j*8, 1);
        asm volatile("fence.proxy.async.shared::cta;" ::: "memory");
    }
    __syncthreads();
    Pipe P{0,0};
    const char* zX = (const char*)g_zeroX;

    // ---- phase 1: E0(t) [0-31] || D0(t) [32-63] || E1(t-1) [64-95] ----
    for (int it = 0; it <= Tt; it++) {
        if (bid < 32 && it < Tt) {
            int t = it, ct = bid;
            const char* bh = t ? (const char*)(g_h0eH + (long)((t-1)&1)*XTC) : zX;
            const char* bl = t ? (const char*)(g_h0eL + (long)((t-1)&1)*XTC) : zX;
            stage_mma(P, dynsmem, smb,
                      (const char*)(g_Ae0H + (long)ct*16*ACH), (const char*)(g_Ae0L + (long)ct*16*ACH),
                      bh, bl, bh, bl, 16, 16, red);
            lstm_fin(red, ct, g_bre, g_zxe + (long)t*G4B, g_c0e, nullptr,
                     g_h0eH + (long)(t&1)*XTC, g_h0eL + (long)(t&1)*XTC);
        } else if (bid >= 32 && bid < 64 && it < Tt) {
            int t = it, ct = bid - 32;
            const char* bh = t ? (const char*)(g_txH + (long)(t-1)*XTC) : zX;
            const char* bl = t ? (const char*)(g_txL + (long)(t-1)*XTC) : zX;
            stage_mma(P, dynsmem, smb,
                      (const char*)(g_Ad0H + (long)ct*16*ACH), (const char*)(g_Ad0L + (long)ct*16*ACH),
                      bh, bl, bh, bl, 16, 16, red);
            lstm_fin(red, ct, g_brd, g_zxd + (long)t*G4B, g_c0d, nullptr,
                     g_txH + (long)t*XTC, g_txL + (long)t*XTC);
        } else if (bid >= 64 && bid < 96 && it >= 1) {
            int t = it - 1, ct = bid - 64;
            const char* b1h = (const char*)(g_h0eH + (long)(t&1)*XTC);
            const char* b1l = (const char*)(g_h0eL + (long)(t&1)*XTC);
            const char* b2h = t ? (const char*)(g_encSH + (long)((t-1)&1)*XTC) : zX;
            const char* b2l = t ? (const char*)(g_encSL + (long)((t-1)&1)*XTC) : zX;
            stage_mma(P, dynsmem, smb,
                      (const char*)(g_Ae1H + (long)ct*32*ACH), (const char*)(g_Ae1L + (long)ct*32*ACH),
                      b1h, b1l, b2h, b2l, 16, 32, red);
            lstm_fin(red, ct, g_bre + G4, nullptr, g_c1e, g_encHs + (long)t*HB,
                     g_encSH + (long)(t&1)*XTC, g_encSL + (long)(t&1)*XTC);
        }
        gbar(tgt);
    }

    // ---- phase 2 ----
    for (int t = 0; t < Tt; t++) {
        int p = t & 1;
        float* h1cur = g_h1d + p*HB;
        // S1: dec layer1 (blocks 0-31)
        if (bid < 32) {
            int ct = bid;
            const char* b1h = (const char*)(g_txH + (long)t*XTC);
            const char* b1l = (const char*)(g_txL + (long)t*XTC);
            const char* b2h = t ? (const char*)(g_h1SH + (long)(1-p)*XTC) : zX;
            const char* b2l = t ? (const char*)(g_h1SL + (long)(1-p)*XTC) : zX;
            stage_mma(P, dynsmem, smb,
                      (const char*)(g_Ad1H + (long)ct*32*ACH), (const char*)(g_Ad1L + (long)ct*32*ACH),
                      b1h, b1l, b2h, b2l, 16, 32, red);
            lstm_fin(red, ct, g_brd + G4, nullptr, g_c1d, h1cur,
                     g_h1SH + (long)p*XTC, g_h1SL + (long)p*XTC);
        }
        gbar(tgt);

        // S2: scores (0-63) || S4h: W_c h-half (64-79)
        if (bid < Tt) {
            const float* e = g_encHs + (long)bid*HB;
            float s = 0.f;
            #pragma unroll 4
            for (int hh = wid*32; hh < wid*32 + 32; hh++)
                s += h1cur[hh*Bb + lane] * e[hh*Bb + lane];
            attw[wid*33 + lane] = s;
            __syncthreads();
            if (wid == 0) {
                float a = 0.f;
                #pragma unroll
                for (int j = 0; j < 32; j++) a += attw[j*33 + lane];
                g_scoresT[bid*Bb + lane] = a;
            }
            __syncthreads();
        } else if (bid < 80) {
            int idx = bid - 64, ct = idx >> 1, kq = idx & 1;
            stage_mma(P, dynsmem, smb,
                      (const char*)(g_AwcH + (long)(ct*32 + kq*8)*ACH),
                      (const char*)(g_AwcL + (long)(ct*32 + kq*8)*ACH),
                      (const char*)(g_h1SH + (long)p*XTC + (long)kq*8*BCH),
                      (const char*)(g_h1SL + (long)p*XTC + (long)kq*8*BCH),
                      (const char*)g_ctxH, (const char*)g_ctxL, 8, 8, red);
            for (int i = tid; i < 4096; i += NTHR) {
                int cl = i >> 5, b = i & 31;
                g_wcP[(long)kq*HB + (ct*128 + cl)*32 + b] =
                    red[cl*33 + b] + red[4224 + cl*33 + b];
            }
            __syncthreads();
        }
        gbar(tgt);

        // S3: softmax + ctx
        if (wid == 0) {
            float mx = -1e30f;
            #pragma unroll
            for (int q = 0; q < Tt; q++) mx = fmaxf(mx, g_scoresT[q*Bb + lane]);
            float sum = 0.f;
            #pragma unroll
            for (int q = 0; q < Tt; q++) {
                float e = expf(g_scoresT[q*Bb + lane] - mx);
                attw[q*33 + lane] = e; sum += e;
            }
            float inv = 1.f/sum;
            #pragma unroll
            for (int q = 0; q < Tt; q++) attw[q*33 + lane] *= inv;
        }
        __syncthreads();
        if (wid < 8) {
            int hh = bid*8 + wid;
            float s = 0.f;
            #pragma unroll 8
            for (int q = 0; q < Tt; q++)
                s += attw[q*33 + lane] * g_encHs[((long)q*Hh + hh)*Bb + lane];
            stX(g_ctxH, g_ctxL, lane, hh, s);
        }
        gbar(tgt);

        // S4c: W_c ctx-half (blocks 0-15)
        if (bid < 16) {
            int ct = bid >> 1, kq = bid & 1;
            stage_mma(P, dynsmem, smb,
                      (const char*)(g_AwcH + (long)(ct*32 + 16 + kq*8)*ACH),
                      (const char*)(g_AwcL + (long)(ct*32 + 16 + kq*8)*ACH),
                      (const char*)(g_ctxH + (long)kq*8*BCH),
                      (const char*)(g_ctxL + (long)kq*8*BCH),
                      (const char*)g_ctxH, (const char*)g_ctxL, 8, 8, red);
            for (int i = tid; i < 4096; i += NTHR) {
                int cl = i >> 5, b = i & 31;
                g_wcP[(long)(2 + kq)*HB + (ct*128 + cl)*32 + b] =
                    red[cl*33 + b] + red[4224 + cl*33 + b];
            }
            __syncthreads();
        }
        gbar(tgt);

        // S4b: reduce -> ht (blocks 0-7)
        if (bid < 8) {
            for (int i = tid; i < 4096; i += NTHR) {
                int cl = i >> 5, b = i & 31;
                int col = bid*128 + cl;
                float v = b_c[col];
                #pragma unroll
                for (int s4 = 0; s4 < 4; s4++) v += g_wcP[(long)s4*HB + col*32 + b];
                stX(g_htH, g_htL, b, col, v);
            }
            __syncthreads();
        }
        gbar(tgt);

        // S5: proj split-K (blocks 0-15)
        if (bid < 16) {
            int ct = bid >> 2, kq = bid & 3;
            stage_mma(P, dynsmem, smb,
                      (const char*)(g_ApjH + (long)(ct*16 + kq*4)*ACH),
                      (const char*)(g_ApjL + (long)(ct*16 + kq*4)*ACH),
                      (const char*)(g_htH + (long)kq*4*BCH),
                      (const char*)(g_htL + (long)kq*4*BCH),
                      (const char*)g_htH, (const char*)g_htL, 4, 4, red);
            for (int i = tid; i < 4096; i += NTHR) {
                int cl = i >> 5, b = i & 31;
                g_oeP[(long)kq*(Ee*Bb) + (ct*128 + cl)*32 + b] =
                    red[cl*33 + b] + red[4224 + cl*33 + b];
            }
            __syncthreads();
        }
        gbar(tgt);

        // S5b: reduce -> oe bf16 hi/lo (blocks 0-3)
        if (bid < 4) {
            for (int i = tid; i < 4096; i += NTHR) {
                int cl = i >> 5, b = i & 31;
                int col = bid*128 + cl;
                float v = proj_b[col];
                #pragma unroll
                for (int s4 = 0; s4 < 4; s4++) v += g_oeP[(long)s4*(Ee*Bb) + col*32 + b];
                splitw(v, g_oeH, g_oeL, (long)(t*32 + b)*Ee + col);
            }
            __syncthreads();
        }
    }
}

// ---------------- HMMA vocab GEMM + exp epilogue (ldmatrix) ----------------
#define LP 40
__global__ void __launch_bounds__(512) logits_hmma(const float* __restrict__ bias,
                                                   float* __restrict__ E) {
    __shared__ bf16 Ah[128*LP], Al[128*LP], Bh[128*LP], Bl[128*LP];
    int tid = threadIdx.x, lane = tid & 31, wid = tid >> 5;
    int gr = lane >> 2, tig = lane & 3;
    int wm = wid >> 2, wn = wid & 3;
    int bn = blockIdx.x*128, bm = blockIdx.y*128;
    int r = tid & 127, seg = tid >> 7;
    uint32_t sAh = s2u(Ah), sAl = s2u(Al), sBh = s2u(Bh), sBl = s2u(Bl);
    uint32_t aoff = (uint32_t)((lane & 15)*(LP*2) + ((lane >> 4) << 4));
    uint32_t boff = (uint32_t)((((lane >> 4) << 3) + (lane & 7))*(LP*2) + (((lane >> 3) & 1) << 4));
    float acc[2][4][4] = {};
    for (int k0 = 0; k0 < 512; k0 += 32) {
        *(uint4*)&Ah[r*LP + seg*8] = *(const uint4*)&g_oeH[(long)(bm+r)*Ee + k0 + seg*8];
        *(uint4*)&Al[r*LP + seg*8] = *(const uint4*)&g_oeL[(long)(bm+r)*Ee + k0 + seg*8];
        *(uint4*)&Bh[r*LP + seg*8] = *(const uint4*)&g_WoTH[(long)(bn+r)*Ee + k0 + seg*8];
        *(uint4*)&Bl[r*LP + seg*8] = *(const uint4*)&g_WoTL[(long)(bn+r)*Ee + k0 + seg*8];
        __syncthreads();
        #pragma unroll
        for (int ks = 0; ks < 2; ks++) {
            uint32_t kadd = (uint32_t)(ks << 5);
            uint32_t bh4[2][4], bl4[2][4];
            #pragma unroll
            for (int nfp = 0; nfp < 2; nfp++) {
                uint32_t bb = (uint32_t)((wn*32 + nfp*16)*(LP*2)) + kadd + boff;
                ldsm4(bh4[nfp], sBh + bb);
                ldsm4(bl4[nfp], sBl + bb);
            }
            #pragma unroll
            for (int mt = 0; mt < 2; mt++) {
                uint32_t ab = (uint32_t)((wm*32 + mt*16)*(LP*2)) + kadd + aoff;
                uint32_t a4[4], a4l[4];
                ldsm4(a4,  sAh + ab);
                ldsm4(a4l, sAl + ab);
                #pragma unroll
                for (int nfp = 0; nfp < 2; nfp++) {
                    hmma(acc[mt][nfp*2],   a4,  bh4[nfp]);
                    hmma(acc[mt][nfp*2],   a4l, bh4[nfp]);
                    hmma(acc[mt][nfp*2],   a4,  bl4[nfp]);
                    hmma(acc[mt][nfp*2+1], a4,  bh4[nfp] + 2);
                    hmma(acc[mt][nfp*2+1], a4l, bh4[nfp] + 2);
                    hmma(acc[mt][nfp*2+1], a4,  bl4[nfp] + 2);
                }
            }
        }
        __syncthreads();
    }
    #pragma unroll
    for (int mt = 0; mt < 2; mt++)
        #pragma unroll
        for (int nf = 0; nf < 4; nf++) {
            int row = bm + wm*32 + mt*16 + gr;
            int col = bn + wn*32 + nf*8 + tig*2;
            float b0 = bias[col], b1 = bias[col+1];
            float* e0 = E + (size_t)row*VTv + col;
            e0[0] = expf(acc[mt][nf][0] + b0);
            e0[1] = expf(acc[mt][nf][1] + b1);
            float* e1 = E + (size_t)(row+8)*VTv + col;
            e1[0] = expf(acc[mt][nf][2] + b0);
            e1[1] = expf(acc[mt][nf][3] + b1);
        }
}

__global__ void softmax_norm(const float* __restrict__ E, float* __restrict__ out) {
    int m = blockIdx.x;
    const float* er = E + (size_t)m*VTv;
    int tid = threadIdx.x;
    __shared__ float red[256];
    float sum = 0.f;
    for (int i = tid; i < VTv; i += 256) sum += er[i];
    red[tid] = sum; __syncthreads();
    for (int s = 128; s; s >>= 1) { if (tid < s) red[tid] += red[tid+s]; __syncthreads(); }
    float inv = 1.f/red[0];
    int t = m >> 5, b = m & 31;
    float* orow = out + (size_t)(b*Tt + t)*VTv;
    for (int i = tid; i < VTv; i += 256) orow[i] = er[i]*inv;
}

// ---------------- host ----------------
extern "C" void kernel_launch(void* const* d_in, const int* in_sizes, int n_in,
                              void* d_out, int out_size) {
    const int*   src    = (const int*)d_in[0];
    const int*   tgt    = (const int*)d_in[1];
    const float* s_emb  = (const float*)d_in[2];
    const float* s_pW   = (const float*)d_in[3];
    const float* s_pb   = (const float*)d_in[4];
    const float* t_emb  = (const float*)d_in[5];
    const float* t_pW   = (const float*)d_in[6];
    const float* t_pb   = (const float*)d_in[7];
    const float* enc_W  = (const float*)d_in[8];
    const float* enc_b  = (const float*)d_in[9];
    const float* dec_W  = (const float*)d_in[10];
    const float* dec_b  = (const float*)d_in[11];
    const float* W_c    = (const float*)d_in[12];
    const float* b_c    = (const float*)d_in[13];
    const float* proj_W = (const float*)d_in[14];
    const float* proj_b = (const float*)d_in[15];
    const float* proj_Wo= (const float*)d_in[16];
    const float* proj_bo= (const float*)d_in[17];
    float* out = (float*)d_out;

    float* elog;
    cudaGetSymbolAddress((void**)&elog, g_elog);

    cudaFuncSetAttribute(seq_kernel, cudaFuncAttributeMaxDynamicSharedMemorySize, SMEM_SEQ);
    cudaFuncSetAttribute(xgate_mma,  cudaFuncAttributeMaxDynamicSharedMemorySize, SMEM_SEQ);

    prep<<<dim3(4096,4), 256>>>(enc_W, enc_b, dec_W, dec_b, W_c, proj_W);
    transWo<<<dim3(1000,16), dim3(32,8)>>>(proj_Wo);
    embed2<<<dim3(32,64,2), 256>>>(src, tgt, s_emb, t_emb,
                                   (const float4*)s_pW, (const float4*)s_pb,
                                   (const float4*)t_pW, (const float4*)t_pb);
    xgate_mma<<<dim3(32,64,2), NTHR, SMEM_SEQ>>>();
    seq_kernel<<<NBLK, NTHR, SMEM_SEQ>>>(b_c, proj_b);
    logits_hmma<<<dim3(VTv/128, 2048/128), 512>>>(proj_bo, elog);
    softmax_norm<<<Tt*Bb, 256>>>(elog, out);
}

// round 15
// speedup vs baseline: 1.3852x; 1.3852x over previous
#include <cuda_runtime.h>
#include <cuda_bf16.h>
#include <math.h>
#include <stdint.h>

#define Bb 32
#define Tt 64
#define Ee 512
#define Hh 1024
#define VTv 32000
#define HB (Hh*Bb)
#define G4 (4*Hh)
#define G4B (G4*Bb)
#define NBLK 128
#define NTHR 512

typedef unsigned long long u64;
typedef __nv_bfloat16 bf16;

__device__ __forceinline__ float sigf(float x) { return 1.f/(1.f+expf(-x)); }
__device__ __forceinline__ uint32_t s2u(const void* p) {
    uint32_t a;
    asm("{ .reg .u64 t; cvta.to.shared.u64 t, %1; cvt.u32.u64 %0, t; }" : "=r"(a) : "l"(p));
    return a;
}
__device__ __forceinline__ void mb_init(uint32_t m, uint32_t c) {
    asm volatile("mbarrier.init.shared.b64 [%0], %1;" :: "r"(m), "r"(c) : "memory");
}
__device__ __forceinline__ void mb_expect(uint32_t m, uint32_t b) {
    asm volatile("mbarrier.arrive.expect_tx.shared.b64 _, [%0], %1;" :: "r"(m), "r"(b) : "memory");
}
__device__ __forceinline__ void mb_wait(uint32_t m, int par) {
    uint32_t done;
    do {
        asm volatile(
            "{\n\t.reg .pred p;\n\t"
            "mbarrier.try_wait.parity.acquire.cta.shared::cta.b64 p, [%1], %2;\n\t"
            "selp.b32 %0,1,0,p;\n\t}"
            : "=r"(done) : "r"(m), "r"((uint32_t)par) : "memory");
    } while (!done);
}
__device__ __forceinline__ void bulk_g2s(uint32_t d, const void* s, uint32_t b, uint32_t m) {
    asm volatile(
        "cp.async.bulk.shared::cluster.global.mbarrier::complete_tx::bytes [%0], [%1], %2, [%3];"
        :: "r"(d), "l"(s), "r"(b), "r"(m) : "memory");
}
__device__ __forceinline__ void hmma(float* c, const uint32_t* a, const uint32_t* b) {
    asm volatile("mma.sync.aligned.m16n8k16.row.col.f32.bf16.bf16.f32 "
        "{%0,%1,%2,%3}, {%4,%5,%6,%7}, {%8,%9}, {%0,%1,%2,%3};"
        : "+f"(c[0]), "+f"(c[1]), "+f"(c[2]), "+f"(c[3])
        : "r"(a[0]), "r"(a[1]), "r"(a[2]), "r"(a[3]), "r"(b[0]), "r"(b[1]));
}
__device__ __forceinline__ void ldsm4(uint32_t* r, uint32_t a) {
    asm volatile("ldmatrix.sync.aligned.m8n8.x4.shared.b16 {%0,%1,%2,%3}, [%4];"
        : "=r"(r[0]), "=r"(r[1]), "=r"(r[2]), "=r"(r[3]) : "r"(a));
}

// padded-row layout: 72 halves (144B rows, 16B-aligned for ldmatrix)
#define ACH 9216
#define ACHB 18432
#define BCH 2304
#define BCHB 4608
#define XTC 36864

// ---------------- device globals ----------------
__device__ __align__(16) float g_encHs[Tt*HB];
__device__ __align__(16) float g_h1d[2*HB];
__device__ __align__(16) float g_c0e[HB];
__device__ __align__(16) float g_c1e[HB];
__device__ __align__(16) float g_c0d[HB];
__device__ __align__(16) float g_c1d[HB];
__device__ __align__(16) float g_scoresT[Tt*Bb];
__device__ __align__(16) float g_bre[2*G4];
__device__ __align__(16) float g_brd[2*G4];
__device__ __align__(16) float g_zxe[Tt*G4B];
__device__ __align__(16) float g_zxd[Tt*G4B];
__device__ __align__(16) float g_wcP[4*Hh*Bb];
__device__ __align__(16) float g_oeP[4*Ee*Bb];
__device__ __align__(16) float g_elog[(size_t)Tt*Bb*VTv];
__device__ __align__(16) bf16 g_AxeH[32*16*ACH]; __device__ __align__(16) bf16 g_AxeL[32*16*ACH];
__device__ __align__(16) bf16 g_Ae0H[32*16*ACH]; __device__ __align__(16) bf16 g_Ae0L[32*16*ACH];
__device__ __align__(16) bf16 g_Ae1H[32*32*ACH]; __device__ __align__(16) bf16 g_Ae1L[32*32*ACH];
__device__ __align__(16) bf16 g_AxdH[32*16*ACH]; __device__ __align__(16) bf16 g_AxdL[32*16*ACH];
__device__ __align__(16) bf16 g_Ad0H[32*16*ACH]; __device__ __align__(16) bf16 g_Ad0L[32*16*ACH];
__device__ __align__(16) bf16 g_Ad1H[32*32*ACH]; __device__ __align__(16) bf16 g_Ad1L[32*32*ACH];
__device__ __align__(16) bf16 g_AwcH[8*32*ACH];  __device__ __align__(16) bf16 g_AwcL[8*32*ACH];
__device__ __align__(16) bf16 g_ApjH[4*16*ACH];  __device__ __align__(16) bf16 g_ApjL[4*16*ACH];
__device__ __align__(16) bf16 g_XsH[64*XTC]; __device__ __align__(16) bf16 g_XsL[64*XTC];
__device__ __align__(16) bf16 g_XtH[64*XTC]; __device__ __align__(16) bf16 g_XtL[64*XTC];
__device__ __align__(16) bf16 g_txH[64*XTC]; __device__ __align__(16) bf16 g_txL[64*XTC];
__device__ __align__(16) bf16 g_h0eH[2*XTC]; __device__ __align__(16) bf16 g_h0eL[2*XTC];
__device__ __align__(16) bf16 g_encSH[2*XTC];__device__ __align__(16) bf16 g_encSL[2*XTC];
__device__ __align__(16) bf16 g_h1SH[2*XTC]; __device__ __align__(16) bf16 g_h1SL[2*XTC];
__device__ __align__(16) bf16 g_ctxH[XTC];   __device__ __align__(16) bf16 g_ctxL[XTC];
__device__ __align__(16) bf16 g_htH[XTC];    __device__ __align__(16) bf16 g_htL[XTC];
__device__ __align__(16) bf16 g_zeroX[XTC];
__device__ __align__(16) bf16 g_oeH[2048*Ee]; __device__ __align__(16) bf16 g_oeL[2048*Ee];
__device__ __align__(16) bf16 g_WoTH[(long)VTv*Ee]; __device__ __align__(16) bf16 g_WoTL[(long)VTv*Ee];
__device__ unsigned g_bar;

#define SLOT_SZ 46080
#define RED_OFF 184320
#define ATT_OFF 218112
#define MBF_OFF 226560
#define SMEM_SEQ 226592

__device__ __forceinline__ void stX(bf16* XH, bf16* XL, int b, int k, float v) {
    bf16 h = __float2bfloat16_rn(v);
    bf16 l = __float2bfloat16_rn(v - __bfloat162float(h));
    int off = ((k >> 6)*32 + b)*72 + (k & 63);
    XH[off] = h; XL[off] = l;
}
__device__ __forceinline__ void splitw(float w, bf16* H, bf16* L, long i) {
    bf16 a = __float2bfloat16_rn(w);
    H[i] = a; L[i] = __float2bfloat16_rn(w - __bfloat162float(a));
}

// ---------------- prep ----------------
__global__ void prep(const float* __restrict__ encW, const float* __restrict__ encb,
                     const float* __restrict__ decW, const float* __restrict__ decb,
                     const float* __restrict__ Wc,   const float* __restrict__ pW) {
    int sec = blockIdx.y;
    long t0 = (long)blockIdx.x*blockDim.x + threadIdx.x;
    long stride = (long)gridDim.x*blockDim.x;
    if (sec < 2) {
        const float* W = sec ? decW : encW;
        bf16 *xh = sec ? g_AxdH : g_AxeH, *xl = sec ? g_AxdL : g_AxeL;
        bf16 *h0h = sec ? g_Ad0H : g_Ae0H, *h0l = sec ? g_Ad0L : g_Ae0L;
        bf16 *l1h = sec ? g_Ad1H : g_Ae1H, *l1l = sec ? g_Ad1L : g_Ae1L;
        for (long q = t0; q < 32L*16*128*64; q += stride) {
            int kl = (int)(q & 63), m = (int)((q>>6)&127);
            int ch = (int)((q>>13)&15), ct = (int)(q>>17);
            long idx = (long)(ct*16 + ch)*ACH + m*72 + kl;
            int col = ct*128 + m;
            long cofs = (long)(col & 3)*1024 + (col >> 2);
            splitw(W[(long)(ch*64 + kl)*4096 + cofs], xh, xl, idx);
            splitw(W[(long)(1024 + ch*64 + kl)*4096 + cofs], h0h, h0l, idx);
        }
        for (long q = t0; q < 32L*32*128*64; q += stride) {
            int kl = (int)(q & 63), m = (int)((q>>6)&127);
            int ch = (int)((q>>13)&31), ct = (int)(q>>18);
            long idx = (long)(ct*32 + ch)*ACH + m*72 + kl;
            int col = ct*128 + m;
            splitw(W[(long)(2048 + ch*64 + kl)*4096 + (long)(col&3)*1024 + (col>>2)],
                   l1h, l1l, idx);
        }
    } else if (sec == 2) {
        for (long q = t0; q < 8L*32*128*64; q += stride) {
            int kl = (int)(q & 63), m = (int)((q>>6)&127);
            int ch = (int)((q>>13)&31), ct = (int)(q>>18);
            long idx = (long)(ct*32 + ch)*ACH + m*72 + kl;
            splitw(Wc[(long)(ch*64 + kl)*1024 + ct*128 + m], g_AwcH, g_AwcL, idx);
        }
        for (long q = t0; q < 4L*16*128*64; q += stride) {
            int kl = (int)(q & 63), m = (int)((q>>6)&127);
            int ch = (int)((q>>13)&15), ct = (int)(q>>17);
            long idx = (long)(ct*16 + ch)*ACH + m*72 + kl;
            splitw(pW[(long)(ch*64 + kl)*512 + ct*128 + m], g_ApjH, g_ApjL, idx);
        }
    } else {
        for (long i = t0; i < 2*G4; i += stride) {
            int l = (int)(i >> 12), col = (int)(i & 4095), n = col>>2, g = col&3;
            g_bre[i] = encb[(l<<12) + g*Hh + n];
            g_brd[i] = decb[(l<<12) + g*Hh + n];
        }
        for (long i = t0; i < HB; i += stride) {
            g_c0e[i]=0.f; g_c1e[i]=0.f; g_c0d[i]=0.f; g_c1d[i]=0.f;
            g_h1d[i]=0.f; g_h1d[i+HB]=0.f;
        }
        bf16 z = __float2bfloat16_rn(0.f);
        for (long i = t0; i < XTC; i += stride) {
            g_zeroX[i] = z;
            g_h1SH[i]=z; g_h1SH[i+XTC]=z; g_h1SL[i]=z; g_h1SL[i+XTC]=z;
        }
        if (t0 == 0) g_bar = 0u;
    }
}

// tiled transpose: proj_Wo[512][32000] -> WoT[32000][512] bf16 hi/lo
__global__ void transWo(const float* __restrict__ Wo) {
    __shared__ float tile[32][33];
    int n0 = blockIdx.x*32, k0 = blockIdx.y*32;
    int tx = threadIdx.x, ty = threadIdx.y;
    #pragma unroll
    for (int i = 0; i < 4; i++)
        tile[ty + i*8][tx] = Wo[(long)(k0 + ty + i*8)*VTv + n0 + tx];
    __syncthreads();
    #pragma unroll
    for (int i = 0; i < 4; i++) {
        float w = tile[tx][ty + i*8];
        splitw(w, g_WoTH, g_WoTL, (long)(n0 + ty + i*8)*Ee + k0 + tx);
    }
}

// ---------------- embedding + input projection -> XT ----------------
__global__ void embed2(const int* __restrict__ src, const int* __restrict__ tgt,
                       const float* __restrict__ s_emb, const float* __restrict__ t_emb,
                       const float4* __restrict__ sW, const float4* __restrict__ sB,
                       const float4* __restrict__ tW, const float4* __restrict__ tB) {
    int z = blockIdx.z;
    const int* tok = z ? tgt : src;
    const float* emb = z ? t_emb : s_emb;
    const float4* W4 = z ? tW : sW;
    const float4* b4 = z ? tB : sB;
    bf16* XH = (z ? g_XtH : g_XsH);
    bf16* XL = (z ? g_XtL : g_XsL);
    int t = blockIdx.y;
    int w = threadIdx.x >> 5, lane = threadIdx.x & 31;
    int n4 = blockIdx.x * 8 + w;
    const float* ar = emb + (long)tok[lane*Tt + t] * Ee;
    float4 acc = b4[n4];
    #pragma unroll 4
    for (int k = 0; k < Ee; k++) {
        float a = ar[k];
        float4 wv = W4[k*(Hh/4) + n4];
        acc.x += a*wv.x; acc.y += a*wv.y; acc.z += a*wv.z; acc.w += a*wv.w;
    }
    bf16* xh = XH + (long)t*XTC;
    bf16* xl = XL + (long)t*XTC;
    stX(xh, xl, lane, n4*4+0, acc.x);
    stX(xh, xl, lane, n4*4+1, acc.y);
    stX(xh, xl, lane, n4*4+2, acc.z);
    stX(xh, xl, lane, n4*4+3, acc.w);
}

// ---------------- HMMA staged GEMM (R13 512-thr layout, splittable) ---------
struct Pipe { uint32_t ph; unsigned base; int iss; };

__device__ void stage_part(Pipe& P, float (&acc)[2][2][4], char* sm, uint32_t smb,
    const char* Ah, const char* Al,
    const char* B1h, const char* B1l, const char* B2h, const char* B2l,
    int nch1, int c0, int c1, int nch_all)
{
    int tid = threadIdx.x, lane = tid & 31, wid = tid >> 5;
    int wm = wid >> 2, wn = (wid >> 1) & 1, wk = wid & 1;
    uint32_t aoff = (uint32_t)((lane & 15)*144 + ((lane >> 4) << 4));
    uint32_t boff = (uint32_t)((((lane >> 4) << 3) + (lane & 7))*144 + (((lane >> 3) & 1) << 4));
    for (int it = c0; it < c1; it++) {
        if (tid == 0) {
            for (; P.iss < nch_all && P.iss <= it + 3; P.iss++) {
                int sl = (int)((P.base + P.iss) & 3);
                uint32_t fb = smb + MBF_OFF + sl*8;
                mb_expect(fb, SLOT_SZ);
                uint32_t d = smb + sl*SLOT_SZ;
                bulk_g2s(d,          Ah + (long)P.iss*ACHB, ACHB, fb);
                bulk_g2s(d + ACHB,   Al + (long)P.iss*ACHB, ACHB, fb);
                const char* bh = (P.iss < nch1) ? B1h + (long)P.iss*BCHB : B2h + (long)(P.iss-nch1)*BCHB;
                const char* bl = (P.iss < nch1) ? B1l + (long)P.iss*BCHB : B2l + (long)(P.iss-nch1)*BCHB;
                bulk_g2s(d + 2*ACHB,        bh, BCHB, fb);
                bulk_g2s(d + 2*ACHB + BCHB, bl, BCHB, fb);
            }
        }
        int sl = (int)((P.base + it) & 3);
        mb_wait(smb + MBF_OFF + sl*8, (P.ph >> sl) & 1);
        P.ph ^= 1u << sl;
        uint32_t d = smb + sl*SLOT_SZ;
        uint32_t dAh = d, dAl = d + ACHB, dBh = d + 2*ACHB, dBl = d + 2*ACHB + BCHB;
        #pragma unroll
        for (int ks = 0; ks < 2; ks++) {
            uint32_t kadd = (uint32_t)((wk*32 + ks*16) << 1);
            uint32_t bh4[4], bl4[4];
            uint32_t bbase = (uint32_t)(wn*16*144) + kadd + boff;
            ldsm4(bh4, dBh + bbase);
            ldsm4(bl4, dBl + bbase);
            #pragma unroll
            for (int mt = 0; mt < 2; mt++) {
                uint32_t abase = (uint32_t)((wm*32 + mt*16)*144) + kadd + aoff;
                uint32_t a4[4], a4l[4];
                ldsm4(a4,  dAh + abase);
                ldsm4(a4l, dAl + abase);
                hmma(acc[mt][0], a4,  bh4);
                hmma(acc[mt][0], a4l, bh4);
                hmma(acc[mt][0], a4,  bl4);
                hmma(acc[mt][1], a4,  bh4 + 2);
                hmma(acc[mt][1], a4l, bh4 + 2);
                hmma(acc[mt][1], a4,  bl4 + 2);
            }
        }
        __syncthreads();
    }
}

__device__ void stage_fin(Pipe& P, float (&acc)[2][2][4], float* red, int nch_all) {
    int tid = threadIdx.x, lane = tid & 31, wid = tid >> 5;
    int wm = wid >> 2, wn = (wid >> 1) & 1, wk = wid & 1;
    int gr = lane >> 2, tig = lane & 3;
    P.base += nch_all;
    float* rw = red + wk*4224;
    #pragma unroll
    for (int mt = 0; mt < 2; mt++)
        #pragma unroll
        for (int nt = 0; nt < 2; nt++) {
            int r0 = wm*32 + mt*16 + gr;
            int cb = wn*16 + nt*8 + tig*2;
            rw[r0*33 + cb]     = acc[mt][nt][0];
            rw[r0*33 + cb + 1] = acc[mt][nt][1];
            rw[(r0+8)*33 + cb]     = acc[mt][nt][2];
            rw[(r0+8)*33 + cb + 1] = acc[mt][nt][3];
        }
    __syncthreads();
}

__device__ void stage_mma(Pipe& P, char* sm, uint32_t smb,
    const char* Ah, const char* Al,
    const char* B1h, const char* B1l, const char* B2h, const char* B2l,
    int nch1, int nch, float* red)
{
    float acc[2][2][4] = {};
    P.iss = 0;
    stage_part(P, acc, sm, smb, Ah, Al, B1h, B1l, B2h, B2l, nch1, 0, nch, nch);
    stage_fin(P, acc, red, nch);
}

__device__ void lstm_fin(const float* red, int ct, const float* __restrict__ bias,
                         const float* __restrict__ zx, float* __restrict__ c,
                         float* __restrict__ hlin, bf16* XH, bf16* XL) {
    for (int i = threadIdx.x; i < 1024; i += NTHR) {
        int nl = i >> 5, b = i & 31;
        int col = ct*128 + nl*4;
        const float* r0 = red + (nl*4)*33 + b;
        const float* r1 = r0 + 4224;
        float zi = r0[0]  + r1[0]  + bias[col];
        float zj = r0[33] + r1[33] + bias[col+1];
        float zf = r0[66] + r1[66] + bias[col+2];
        float zo = r0[99] + r1[99] + bias[col+3];
        if (zx) {
            const float* z = zx + (long)col*32 + b;
            zi += z[0]; zj += z[32]; zf += z[64]; zo += z[96];
        }
        int idx = (ct*32 + nl)*32 + b;
        float cn = c[idx]*sigf(zf + 1.f) + sigf(zi)*tanhf(zj);
        c[idx] = cn;
        float h = tanhf(cn)*sigf(zo);
        if (hlin) hlin[idx] = h;
        stX(XH, XL, b, ct*32 + nl, h);
    }
    __syncthreads();
}

// ---------------- xgate (HMMA) ----------------
__global__ void __launch_bounds__(NTHR) xgate_mma() {
    extern __shared__ __align__(16) char dynsmem[];
    uint32_t smb = s2u(dynsmem);
    float* red = (float*)(dynsmem + RED_OFF);
    if (threadIdx.x == 0) {
        #pragma unroll
        for (int j = 0; j < 4; j++) mb_init(smb + MBF_OFF + j*8, 1);
        asm volatile("fence.proxy.async.shared::cta;" ::: "memory");
    }
    __syncthreads();
    Pipe P{0,0,0};
    int ct = blockIdx.x, t = blockIdx.y, z = blockIdx.z;
    const char* Ah = (const char*)((z ? g_AxdH : g_AxeH) + (long)ct*16*ACH);
    const char* Al = (const char*)((z ? g_AxdL : g_AxeL) + (long)ct*16*ACH);
    const char* Bh = (const char*)((z ? g_XtH : g_XsH) + (long)t*XTC);
    const char* Bl = (const char*)((z ? g_XtL : g_XsL) + (long)t*XTC);
    stage_mma(P, dynsmem, smb, Ah, Al, Bh, Bl, Bh, Bl, 16, 16, red);
    float* out = (z ? g_zxd : g_zxe) + (long)t*G4B;
    for (int i = threadIdx.x; i < 4096; i += NTHR) {
        int cl = i >> 5, b = i & 31;
        out[(long)(ct*128 + cl)*32 + b] = red[cl*33 + b] + red[4224 + cl*33 + b];
    }
}

// ---------------- grid barrier ----------------
__device__ __forceinline__ void gbar(unsigned &tgt) {
    tgt += NBLK;
    __syncthreads();
    if (threadIdx.x == 0) {
        __threadfence();
        atomicAdd(&g_bar, 1u);
        unsigned v;
        do {
            asm volatile("ld.acquire.gpu.u32 %0,[%1];" : "=r"(v) : "l"(&g_bar) : "memory");
        } while (v < tgt);
    }
    __syncthreads();
}

// ---------------- persistent sequence kernel ----------------
__global__ void __launch_bounds__(NTHR,1) seq_kernel(const float* __restrict__ b_c,
                                                     const float* __restrict__ proj_b) {
    extern __shared__ __align__(16) char dynsmem[];
    uint32_t smb = s2u(dynsmem);
    float* red = (float*)(dynsmem + RED_OFF);
    float* attw = (float*)(dynsmem + ATT_OFF);
    int tid = threadIdx.x, lane = tid & 31, wid = tid >> 5, bid = blockIdx.x;
    unsigned tgt = 0;
    if (tid == 0) {
        #pragma unroll
        for (int j = 0; j < 4; j++) mb_init(smb + MBF_OFF + j*8, 1);
        asm volatile("fence.proxy.async.shared::cta;" ::: "memory");
    }
    __syncthreads();
    Pipe P{0,0,0};
    const char* zX = (const char*)g_zeroX;

    // ---- phase 1: E0(t) [0-31] || D0(t) [32-63] || E1(t-1) [64-95] || S1(0) [96-127 @ it==Tt]
    for (int it = 0; it <= Tt; it++) {
        if (bid < 32 && it < Tt) {
            int t = it, ct = bid;
            const char* bh = t ? (const char*)(g_h0eH + (long)((t-1)&1)*XTC) : zX;
            const char* bl = t ? (const char*)(g_h0eL + (long)((t-1)&1)*XTC) : zX;
            stage_mma(P, dynsmem, smb,
                      (const char*)(g_Ae0H + (long)ct*16*ACH), (const char*)(g_Ae0L + (long)ct*16*ACH),
                      bh, bl, bh, bl, 16, 16, red);
            lstm_fin(red, ct, g_bre, g_zxe + (long)t*G4B, g_c0e, nullptr,
                     g_h0eH + (long)(t&1)*XTC, g_h0eL + (long)(t&1)*XTC);
        } else if (bid >= 32 && bid < 64 && it < Tt) {
            int t = it, ct = bid - 32;
            const char* bh = t ? (const char*)(g_txH + (long)(t-1)*XTC) : zX;
            const char* bl = t ? (const char*)(g_txL + (long)(t-1)*XTC) : zX;
            stage_mma(P, dynsmem, smb,
                      (const char*)(g_Ad0H + (long)ct*16*ACH), (const char*)(g_Ad0L + (long)ct*16*ACH),
                      bh, bl, bh, bl, 16, 16, red);
            lstm_fin(red, ct, g_brd, g_zxd + (long)t*G4B, g_c0d, nullptr,
                     g_txH + (long)t*XTC, g_txL + (long)t*XTC);
        } else if (bid >= 64 && bid < 96 && it >= 1) {
            int t = it - 1, ct = bid - 64;
            const char* b1h = (const char*)(g_h0eH + (long)(t&1)*XTC);
            const char* b1l = (const char*)(g_h0eL + (long)(t&1)*XTC);
            const char* b2h = t ? (const char*)(g_encSH + (long)((t-1)&1)*XTC) : zX;
            const char* b2l = t ? (const char*)(g_encSL + (long)((t-1)&1)*XTC) : zX;
            stage_mma(P, dynsmem, smb,
                      (const char*)(g_Ae1H + (long)ct*32*ACH), (const char*)(g_Ae1L + (long)ct*32*ACH),
                      b1h, b1l, b2h, b2l, 16, 32, red);
            lstm_fin(red, ct, g_bre + G4, nullptr, g_c1e, g_encHs + (long)t*HB,
                     g_encSH + (long)(t&1)*XTC, g_encSL + (long)(t&1)*XTC);
        } else if (bid >= 96 && it == Tt) {
            // S1(0): dec layer1 for t=0 (h1prev = 0)
            int ct = bid - 96;
            stage_mma(P, dynsmem, smb,
                      (const char*)(g_Ad1H + (long)ct*32*ACH), (const char*)(g_Ad1L + (long)ct*32*ACH),
                      (const char*)g_txH, (const char*)g_txL, zX, zX, 16, 32, red);
            lstm_fin(red, ct, g_brd + G4, nullptr, g_c1d, g_h1d,
                     g_h1SH, g_h1SL);
        }
        gbar(tgt);
    }

    // ---- phase 2: S1(t+1) overlapped on blocks 96-127 ----
    float s1acc[2][2][4];
    for (int t = 0; t < Tt; t++) {
        int p = t & 1;
        float* h1cur = g_h1d + p*HB;
        int tn = t + 1, pn = tn & 1;
        bool doS1 = (t < Tt - 1);
        const char* s1Ah = (const char*)(g_Ad1H + (long)(bid-96)*32*ACH);
        const char* s1Al = (const char*)(g_Ad1L + (long)(bid-96)*32*ACH);
        const char* s1B1h = (const char*)(g_txH + (long)tn*XTC);
        const char* s1B1l = (const char*)(g_txL + (long)tn*XTC);
        const char* s1B2h = (const char*)(g_h1SH + (long)p*XTC);
        const char* s1B2l = (const char*)(g_h1SL + (long)p*XTC);

        // slotA: scores [0-63] || W_c h-half [64-79] || S1p1 [96-127]
        if (bid < Tt) {
            const float* e = g_encHs + (long)bid*HB;
            float s = 0.f;
            #pragma unroll 4
            for (int hh = wid*64; hh < wid*64 + 64; hh++)
                s += h1cur[hh*Bb + lane] * e[hh*Bb + lane];
            attw[wid*33 + lane] = s;
            __syncthreads();
            if (wid == 0) {
                float a = 0.f;
                #pragma unroll
                for (int j = 0; j < 16; j++) a += attw[j*33 + lane];
                g_scoresT[bid*Bb + lane] = a;
            }
            __syncthreads();
        } else if (bid < 80) {
            int idx = bid - 64, ct = idx >> 1, kq = idx & 1;
            stage_mma(P, dynsmem, smb,
                      (const char*)(g_AwcH + (long)(ct*32 + kq*8)*ACH),
                      (const char*)(g_AwcL + (long)(ct*32 + kq*8)*ACH),
                      (const char*)(g_h1SH + (long)p*XTC + (long)kq*8*BCH),
                      (const char*)(g_h1SL + (long)p*XTC + (long)kq*8*BCH),
                      (const char*)g_ctxH, (const char*)g_ctxL, 8, 8, red);
            for (int i = tid; i < 4096; i += NTHR) {
                int cl = i >> 5, b = i & 31;
                g_wcP[(long)kq*HB + (ct*128 + cl)*32 + b] =
                    red[cl*33 + b] + red[4224 + cl*33 + b];
            }
            __syncthreads();
        } else if (bid >= 96 && doS1) {
            #pragma unroll
            for (int a1 = 0; a1 < 2; a1++)
                #pragma unroll
                for (int a2 = 0; a2 < 2; a2++)
                    #pragma unroll
                    for (int a3 = 0; a3 < 4; a3++) s1acc[a1][a2][a3] = 0.f;
            P.iss = 0;
            stage_part(P, s1acc, dynsmem, smb, s1Ah, s1Al,
                       s1B1h, s1B1l, s1B2h, s1B2l, 16, 0, 8, 32);
        }
        gbar(tgt);

        // slotB: softmax + ctx [0-63] || S1p2 [96-127]
        if (bid < 64) {
            if (wid == 0) {
                float mx = -1e30f;
                #pragma unroll
                for (int q = 0; q < Tt; q++) mx = fmaxf(mx, g_scoresT[q*Bb + lane]);
                float sum = 0.f;
                #pragma unroll
                for (int q = 0; q < Tt; q++) {
                    float e = expf(g_scoresT[q*Bb + lane] - mx);
                    attw[q*33 + lane] = e; sum += e;
                }
                float inv = 1.f/sum;
                #pragma unroll
                for (int q = 0; q < Tt; q++) attw[q*33 + lane] *= inv;
            }
            __syncthreads();
            int hh = bid*16 + wid;
            float s = 0.f;
            #pragma unroll 8
            for (int q = 0; q < Tt; q++)
                s += attw[q*33 + lane] * g_encHs[((long)q*Hh + hh)*Bb + lane];
            stX(g_ctxH, g_ctxL, lane, hh, s);
        } else if (bid >= 96 && doS1) {
            stage_part(P, s1acc, dynsmem, smb, s1Ah, s1Al,
                       s1B1h, s1B1l, s1B2h, s1B2l, 16, 8, 16, 32);
        }
        gbar(tgt);

        // slotC: W_c ctx-half [0-15] || S1p3 [96-127]
        if (bid < 16) {
            int ct = bid >> 1, kq = bid & 1;
            stage_mma(P, dynsmem, smb,
                      (const char*)(g_AwcH + (long)(ct*32 + 16 + kq*8)*ACH),
                      (const char*)(g_AwcL + (long)(ct*32 + 16 + kq*8)*ACH),
                      (const char*)(g_ctxH + (long)kq*8*BCH),
                      (const char*)(g_ctxL + (long)kq*8*BCH),
                      (const char*)g_ctxH, (const char*)g_ctxL, 8, 8, red);
            for (int i = tid; i < 4096; i += NTHR) {
                int cl = i >> 5, b = i & 31;
                g_wcP[(long)(2 + kq)*HB + (ct*128 + cl)*32 + b] =
                    red[cl*33 + b] + red[4224 + cl*33 + b];
            }
            __syncthreads();
        } else if (bid >= 96 && doS1) {
            stage_part(P, s1acc, dynsmem, smb, s1Ah, s1Al,
                       s1B1h, s1B1l, s1B2h, s1B2l, 16, 16, 24, 32);
        }
        gbar(tgt);

        // slotD: reduce -> ht [0-7] || S1p4 + finish [96-127]
        if (bid < 8) {
            for (int i = tid; i < 4096; i += NTHR) {
                int cl = i >> 5, b = i & 31;
                int col = bid*128 + cl;
                float v = b_c[col];
                #pragma unroll
                for (int s4 = 0; s4 < 4; s4++) v += g_wcP[(long)s4*HB + col*32 + b];
                stX(g_htH, g_htL, b, col, v);
            }
            __syncthreads();
        } else if (bid >= 96 && doS1) {
            stage_part(P, s1acc, dynsmem, smb, s1Ah, s1Al,
                       s1B1h, s1B1l, s1B2h, s1B2l, 16, 24, 32, 32);
            stage_fin(P, s1acc, red, 32);
            lstm_fin(red, bid - 96, g_brd + G4, nullptr, g_c1d, g_h1d + (long)pn*HB,
                     g_h1SH + (long)pn*XTC, g_h1SL + (long)pn*XTC);
        }
        gbar(tgt);

        // slotE: proj split-K [0-15]
        if (bid < 16) {
            int ct = bid >> 2, kq = bid & 3;
            stage_mma(P, dynsmem, smb,
                      (const char*)(g_ApjH + (long)(ct*16 + kq*4)*ACH),
                      (const char*)(g_ApjL + (long)(ct*16 + kq*4)*ACH),
                      (const char*)(g_htH + (long)kq*4*BCH),
                      (const char*)(g_htL + (long)kq*4*BCH),
                      (const char*)g_htH, (const char*)g_htL, 4, 4, red);
            for (int i = tid; i < 4096; i += NTHR) {
                int cl = i >> 5, b = i & 31;
                g_oeP[(long)kq*(Ee*Bb) + (ct*128 + cl)*32 + b] =
                    red[cl*33 + b] + red[4224 + cl*33 + b];
            }
            __syncthreads();
        }
        gbar(tgt);

        // slotF: reduce -> oe bf16 hi/lo [0-3] (no trailing barrier)
        if (bid < 4) {
            for (int i = tid; i < 4096; i += NTHR) {
                int cl = i >> 5, b = i & 31;
                int col = bid*128 + cl;
                float v = proj_b[col];
                #pragma unroll
                for (int s4 = 0; s4 < 4; s4++) v += g_oeP[(long)s4*(Ee*Bb) + col*32 + b];
                splitw(v, g_oeH, g_oeL, (long)(t*32 + b)*Ee + col);
            }
            __syncthreads();
        }
    }
}

// ---------------- HMMA vocab GEMM + exp epilogue (ldmatrix) ----------------
#define LP 40
__global__ void __launch_bounds__(512) logits_hmma(const float* __restrict__ bias,
                                                   float* __restrict__ E) {
    __shared__ bf16 Ah[128*LP], Al[128*LP], Bh[128*LP], Bl[128*LP];
    int tid = threadIdx.x, lane = tid & 31, wid = tid >> 5;
    int gr = lane >> 2, tig = lane & 3;
    int wm = wid >> 2, wn = wid & 3;
    int bn = blockIdx.x*128, bm = blockIdx.y*128;
    int r = tid & 127, seg = tid >> 7;
    uint32_t sAh = s2u(Ah), sAl = s2u(Al), sBh = s2u(Bh), sBl = s2u(Bl);
    uint32_t aoff = (uint32_t)((lane & 15)*(LP*2) + ((lane >> 4) << 4));
    uint32_t boff = (uint32_t)((((lane >> 4) << 3) + (lane & 7))*(LP*2) + (((lane >> 3) & 1) << 4));
    float acc[2][4][4] = {};
    for (int k0 = 0; k0 < 512; k0 += 32) {
        *(uint4*)&Ah[r*LP + seg*8] = *(const uint4*)&g_oeH[(long)(bm+r)*Ee + k0 + seg*8];
        *(uint4*)&Al[r*LP + seg*8] = *(const uint4*)&g_oeL[(long)(bm+r)*Ee + k0 + seg*8];
        *(uint4*)&Bh[r*LP + seg*8] = *(const uint4*)&g_WoTH[(long)(bn+r)*Ee + k0 + seg*8];
        *(uint4*)&Bl[r*LP + seg*8] = *(const uint4*)&g_WoTL[(long)(bn+r)*Ee + k0 + seg*8];
        __syncthreads();
        #pragma unroll
        for (int ks = 0; ks < 2; ks++) {
            uint32_t kadd = (uint32_t)(ks << 5);
            uint32_t bh4[2][4], bl4[2][4];
            #pragma unroll
            for (int nfp = 0; nfp < 2; nfp++) {
                uint32_t bb = (uint32_t)((wn*32 + nfp*16)*(LP*2)) + kadd + boff;
                ldsm4(bh4[nfp], sBh + bb);
                ldsm4(bl4[nfp], sBl + bb);
            }
            #pragma unroll
            for (int mt = 0; mt < 2; mt++) {
                uint32_t ab = (uint32_t)((wm*32 + mt*16)*(LP*2)) + kadd + aoff;
                uint32_t a4[4], a4l[4];
                ldsm4(a4,  sAh + ab);
                ldsm4(a4l, sAl + ab);
                #pragma unroll
                for (int nfp = 0; nfp < 2; nfp++) {
                    hmma(acc[mt][nfp*2],   a4,  bh4[nfp]);
                    hmma(acc[mt][nfp*2],   a4l, bh4[nfp]);
                    hmma(acc[mt][nfp*2],   a4,  bl4[nfp]);
                    hmma(acc[mt][nfp*2+1], a4,  bh4[nfp] + 2);
                    hmma(acc[mt][nfp*2+1], a4l, bh4[nfp] + 2);
                    hmma(acc[mt][nfp*2+1], a4,  bl4[nfp] + 2);
                }
            }
        }
        __syncthreads();
    }
    #pragma unroll
    for (int mt = 0; mt < 2; mt++)
        #pragma unroll
        for (int nf = 0; nf < 4; nf++) {
            int row = bm + wm*32 + mt*16 + gr;
            int col = bn + wn*32 + nf*8 + tig*2;
            float b0 = bias[col], b1 = bias[col+1];
            float* e0 = E + (size_t)row*VTv + col;
            e0[0] = expf(acc[mt][nf][0] + b0);
            e0[1] = expf(acc[mt][nf][1] + b1);
            float* e1 = E + (size_t)(row+8)*VTv + col;
            e1[0] = expf(acc[mt][nf][2] + b0);
            e1[1] = expf(acc[mt][nf][3] + b1);
        }
}

__global__ void softmax_norm(const float* __restrict__ E, float* __restrict__ out) {
    int m = blockIdx.x;
    const float* er = E + (size_t)m*VTv;
    int tid = threadIdx.x;
    __shared__ float red[256];
    float sum = 0.f;
    for (int i = tid; i < VTv; i += 256) sum += er[i];
    red[tid] = sum; __syncthreads();
    for (int s = 128; s; s >>= 1) { if (tid < s) red[tid] += red[tid+s]; __syncthreads(); }
    float inv = 1.f/red[0];
    int t = m >> 5, b = m & 31;
    float* orow = out + (size_t)(b*Tt + t)*VTv;
    for (int i = tid; i < VTv; i += 256) orow[i] = er[i]*inv;
}

// ---------------- host ----------------
extern "C" void kernel_launch(void* const* d_in, const int* in_sizes, int n_in,
                              void* d_out, int out_size) {
    const int*   src    = (const int*)d_in[0];
    const int*   tgt    = (const int*)d_in[1];
    const float* s_emb  = (const float*)d_in[2];
    const float* s_pW   = (const float*)d_in[3];
    const float* s_pb   = (const float*)d_in[4];
    const float* t_emb  = (const float*)d_in[5];
    const float* t_pW   = (const float*)d_in[6];
    const float* t_pb   = (const float*)d_in[7];
    const float* enc_W  = (const float*)d_in[8];
    const float* enc_b  = (const float*)d_in[9];
    const float* dec_W  = (const float*)d_in[10];
    const float* dec_b  = (const float*)d_in[11];
    const float* W_c    = (const float*)d_in[12];
    const float* b_c    = (const float*)d_in[13];
    const float* proj_W = (const float*)d_in[14];
    const float* proj_b = (const float*)d_in[15];
    const float* proj_Wo= (const float*)d_in[16];
    const float* proj_bo= (const float*)d_in[17];
    float* out = (float*)d_out;

    float* elog;
    cudaGetSymbolAddress((void**)&elog, g_elog);

    cudaFuncSetAttribute(seq_kernel, cudaFuncAttributeMaxDynamicSharedMemorySize, SMEM_SEQ);
    cudaFuncSetAttribute(xgate_mma,  cudaFuncAttributeMaxDynamicSharedMemorySize, SMEM_SEQ);

    prep<<<dim3(4096,4), 256>>>(enc_W, enc_b, dec_W, dec_b, W_c, proj_W);
    transWo<<<dim3(1000,16), dim3(32,8)>>>(proj_Wo);
    embed2<<<dim3(32,64,2), 256>>>(src, tgt, s_emb, t_emb,
                                   (const float4*)s_pW, (const float4*)s_pb,
                                   (const float4*)t_pW, (const float4*)t_pb);
    xgate_mma<<<dim3(32,64,2), NTHR, SMEM_SEQ>>>();
    seq_kernel<<<NBLK, NTHR, SMEM_SEQ>>>(b_c, proj_b);
    logits_hmma<<<dim3(VTv/128, 2048/128), 512>>>(proj_bo, elog);
    softmax_norm<<<Tt*Bb, 256>>>(elog, out);
}

// round 16
// speedup vs baseline: 1.4990x; 1.0822x over previous
#include <cuda_runtime.h>
#include <cuda_bf16.h>
#include <math.h>
#include <stdint.h>

#define Bb 32
#define Tt 64
#define Ee 512
#define Hh 1024
#define VTv 32000
#define HB (Hh*Bb)
#define G4 (4*Hh)
#define G4B (G4*Bb)
#define NBLK 128
#define NTHR 512

typedef unsigned long long u64;
typedef __nv_bfloat16 bf16;

__device__ __forceinline__ float sigf(float x) { return 1.f/(1.f+expf(-x)); }
__device__ __forceinline__ uint32_t s2u(const void* p) {
    uint32_t a;
    asm("{ .reg .u64 t; cvta.to.shared.u64 t, %1; cvt.u32.u64 %0, t; }" : "=r"(a) : "l"(p));
    return a;
}
__device__ __forceinline__ void mb_init(uint32_t m, uint32_t c) {
    asm volatile("mbarrier.init.shared.b64 [%0], %1;" :: "r"(m), "r"(c) : "memory");
}
__device__ __forceinline__ void mb_expect(uint32_t m, uint32_t b) {
    asm volatile("mbarrier.arrive.expect_tx.shared.b64 _, [%0], %1;" :: "r"(m), "r"(b) : "memory");
}
__device__ __forceinline__ void mb_wait(uint32_t m, int par) {
    uint32_t done;
    do {
        asm volatile(
            "{\n\t.reg .pred p;\n\t"
            "mbarrier.try_wait.parity.acquire.cta.shared::cta.b64 p, [%1], %2;\n\t"
            "selp.b32 %0,1,0,p;\n\t}"
            : "=r"(done) : "r"(m), "r"((uint32_t)par) : "memory");
    } while (!done);
}
__device__ __forceinline__ void bulk_g2s(uint32_t d, const void* s, uint32_t b, uint32_t m) {
    asm volatile(
        "cp.async.bulk.shared::cluster.global.mbarrier::complete_tx::bytes [%0], [%1], %2, [%3];"
        :: "r"(d), "l"(s), "r"(b), "r"(m) : "memory");
}
__device__ __forceinline__ void hmma(float* c, const uint32_t* a, const uint32_t* b) {
    asm volatile("mma.sync.aligned.m16n8k16.row.col.f32.bf16.bf16.f32 "
        "{%0,%1,%2,%3}, {%4,%5,%6,%7}, {%8,%9}, {%0,%1,%2,%3};"
        : "+f"(c[0]), "+f"(c[1]), "+f"(c[2]), "+f"(c[3])
        : "r"(a[0]), "r"(a[1]), "r"(a[2]), "r"(a[3]), "r"(b[0]), "r"(b[1]));
}
__device__ __forceinline__ void ldsm4(uint32_t* r, uint32_t a) {
    asm volatile("ldmatrix.sync.aligned.m8n8.x4.shared.b16 {%0,%1,%2,%3}, [%4];"
        : "=r"(r[0]), "=r"(r[1]), "=r"(r[2]), "=r"(r[3]) : "r"(a));
}

// padded-row layout: 72 halves (144B rows, 16B-aligned for ldmatrix)
#define ACH 9216
#define ACHB 18432
#define BCH 2304
#define BCHB 4608
#define XTC 36864

// ---------------- device globals ----------------
__device__ __align__(16) float g_encHs[Tt*HB];
__device__ __align__(16) float g_h1d[2*HB];
__device__ __align__(16) float g_c0e[HB];
__device__ __align__(16) float g_c1e[HB];
__device__ __align__(16) float g_c0d[HB];
__device__ __align__(16) float g_c1d[HB];
__device__ __align__(16) float g_scoresT[Tt*Bb];
__device__ __align__(16) float g_bre[2*G4];
__device__ __align__(16) float g_brd[2*G4];
__device__ __align__(16) float g_zxe[Tt*G4B];
__device__ __align__(16) float g_zxd[Tt*G4B];
__device__ __align__(16) float g_wcP[4*Hh*Bb];
__device__ __align__(16) float g_oeP[4*Ee*Bb];
__device__ __align__(16) float g_e1P[2*32*4096];
__device__ __align__(16) float g_elog[(size_t)Tt*Bb*VTv];
__device__ __align__(16) bf16 g_AxeH[32*16*ACH]; __device__ __align__(16) bf16 g_AxeL[32*16*ACH];
__device__ __align__(16) bf16 g_Ae0H[32*16*ACH]; __device__ __align__(16) bf16 g_Ae0L[32*16*ACH];
__device__ __align__(16) bf16 g_Ae1H[32*32*ACH]; __device__ __align__(16) bf16 g_Ae1L[32*32*ACH];
__device__ __align__(16) bf16 g_AxdH[32*16*ACH]; __device__ __align__(16) bf16 g_AxdL[32*16*ACH];
__device__ __align__(16) bf16 g_Ad0H[32*16*ACH]; __device__ __align__(16) bf16 g_Ad0L[32*16*ACH];
__device__ __align__(16) bf16 g_Ad1H[32*32*ACH]; __device__ __align__(16) bf16 g_Ad1L[32*32*ACH];
__device__ __align__(16) bf16 g_AwcH[8*32*ACH];  __device__ __align__(16) bf16 g_AwcL[8*32*ACH];
__device__ __align__(16) bf16 g_ApjH[4*16*ACH];  __device__ __align__(16) bf16 g_ApjL[4*16*ACH];
__device__ __align__(16) bf16 g_XsH[64*XTC]; __device__ __align__(16) bf16 g_XsL[64*XTC];
__device__ __align__(16) bf16 g_XtH[64*XTC]; __device__ __align__(16) bf16 g_XtL[64*XTC];
__device__ __align__(16) bf16 g_txH[64*XTC]; __device__ __align__(16) bf16 g_txL[64*XTC];
__device__ __align__(16) bf16 g_h0eH[2*XTC]; __device__ __align__(16) bf16 g_h0eL[2*XTC];
__device__ __align__(16) bf16 g_encSH[2*XTC];__device__ __align__(16) bf16 g_encSL[2*XTC];
__device__ __align__(16) bf16 g_h1SH[2*XTC]; __device__ __align__(16) bf16 g_h1SL[2*XTC];
__device__ __align__(16) bf16 g_ctxH[XTC];   __device__ __align__(16) bf16 g_ctxL[XTC];
__device__ __align__(16) bf16 g_htH[XTC];    __device__ __align__(16) bf16 g_htL[XTC];
__device__ __align__(16) bf16 g_zeroX[XTC];
__device__ __align__(16) bf16 g_oeH[2048*Ee]; __device__ __align__(16) bf16 g_oeL[2048*Ee];
__device__ __align__(16) bf16 g_WoTH[(long)VTv*Ee]; __device__ __align__(16) bf16 g_WoTL[(long)VTv*Ee];
__device__ unsigned g_bar;

#define SLOT_SZ 46080
#define RED_OFF 184320
#define ATT_OFF 218112
#define MBF_OFF 226560
#define SMEM_SEQ 226592

__device__ __forceinline__ void stX(bf16* XH, bf16* XL, int b, int k, float v) {
    bf16 h = __float2bfloat16_rn(v);
    bf16 l = __float2bfloat16_rn(v - __bfloat162float(h));
    int off = ((k >> 6)*32 + b)*72 + (k & 63);
    XH[off] = h; XL[off] = l;
}
__device__ __forceinline__ void splitw(float w, bf16* H, bf16* L, long i) {
    bf16 a = __float2bfloat16_rn(w);
    H[i] = a; L[i] = __float2bfloat16_rn(w - __bfloat162float(a));
}

// ---------------- prep ----------------
__global__ void prep(const float* __restrict__ encW, const float* __restrict__ encb,
                     const float* __restrict__ decW, const float* __restrict__ decb,
                     const float* __restrict__ Wc,   const float* __restrict__ pW) {
    int sec = blockIdx.y;
    long t0 = (long)blockIdx.x*blockDim.x + threadIdx.x;
    long stride = (long)gridDim.x*blockDim.x;
    if (sec < 2) {
        const float* W = sec ? decW : encW;
        bf16 *xh = sec ? g_AxdH : g_AxeH, *xl = sec ? g_AxdL : g_AxeL;
        bf16 *h0h = sec ? g_Ad0H : g_Ae0H, *h0l = sec ? g_Ad0L : g_Ae0L;
        bf16 *l1h = sec ? g_Ad1H : g_Ae1H, *l1l = sec ? g_Ad1L : g_Ae1L;
        for (long q = t0; q < 32L*16*128*64; q += stride) {
            int kl = (int)(q & 63), m = (int)((q>>6)&127);
            int ch = (int)((q>>13)&15), ct = (int)(q>>17);
            long idx = (long)(ct*16 + ch)*ACH + m*72 + kl;
            int col = ct*128 + m;
            long cofs = (long)(col & 3)*1024 + (col >> 2);
            splitw(W[(long)(ch*64 + kl)*4096 + cofs], xh, xl, idx);
            splitw(W[(long)(1024 + ch*64 + kl)*4096 + cofs], h0h, h0l, idx);
        }
        for (long q = t0; q < 32L*32*128*64; q += stride) {
            int kl = (int)(q & 63), m = (int)((q>>6)&127);
            int ch = (int)((q>>13)&31), ct = (int)(q>>18);
            long idx = (long)(ct*32 + ch)*ACH + m*72 + kl;
            int col = ct*128 + m;
            splitw(W[(long)(2048 + ch*64 + kl)*4096 + (long)(col&3)*1024 + (col>>2)],
                   l1h, l1l, idx);
        }
    } else if (sec == 2) {
        for (long q = t0; q < 8L*32*128*64; q += stride) {
            int kl = (int)(q & 63), m = (int)((q>>6)&127);
            int ch = (int)((q>>13)&31), ct = (int)(q>>18);
            long idx = (long)(ct*32 + ch)*ACH + m*72 + kl;
            splitw(Wc[(long)(ch*64 + kl)*1024 + ct*128 + m], g_AwcH, g_AwcL, idx);
        }
        for (long q = t0; q < 4L*16*128*64; q += stride) {
            int kl = (int)(q & 63), m = (int)((q>>6)&127);
            int ch = (int)((q>>13)&15), ct = (int)(q>>17);
            long idx = (long)(ct*16 + ch)*ACH + m*72 + kl;
            splitw(pW[(long)(ch*64 + kl)*512 + ct*128 + m], g_ApjH, g_ApjL, idx);
        }
    } else {
        for (long i = t0; i < 2*G4; i += stride) {
            int l = (int)(i >> 12), col = (int)(i & 4095), n = col>>2, g = col&3;
            g_bre[i] = encb[(l<<12) + g*Hh + n];
            g_brd[i] = decb[(l<<12) + g*Hh + n];
        }
        for (long i = t0; i < HB; i += stride) {
            g_c0e[i]=0.f; g_c1e[i]=0.f; g_c0d[i]=0.f; g_c1d[i]=0.f;
            g_h1d[i]=0.f; g_h1d[i+HB]=0.f;
        }
        bf16 z = __float2bfloat16_rn(0.f);
        for (long i = t0; i < XTC; i += stride) {
            g_zeroX[i] = z;
            g_h1SH[i]=z; g_h1SH[i+XTC]=z; g_h1SL[i]=z; g_h1SL[i+XTC]=z;
        }
        if (t0 == 0) g_bar = 0u;
    }
}

// tiled transpose: proj_Wo[512][32000] -> WoT[32000][512] bf16 hi/lo
__global__ void transWo(const float* __restrict__ Wo) {
    __shared__ float tile[32][33];
    int n0 = blockIdx.x*32, k0 = blockIdx.y*32;
    int tx = threadIdx.x, ty = threadIdx.y;
    #pragma unroll
    for (int i = 0; i < 4; i++)
        tile[ty + i*8][tx] = Wo[(long)(k0 + ty + i*8)*VTv + n0 + tx];
    __syncthreads();
    #pragma unroll
    for (int i = 0; i < 4; i++) {
        float w = tile[tx][ty + i*8];
        splitw(w, g_WoTH, g_WoTL, (long)(n0 + ty + i*8)*Ee + k0 + tx);
    }
}

// ---------------- embedding + input projection -> XT ----------------
__global__ void embed2(const int* __restrict__ src, const int* __restrict__ tgt,
                       const float* __restrict__ s_emb, const float* __restrict__ t_emb,
                       const float4* __restrict__ sW, const float4* __restrict__ sB,
                       const float4* __restrict__ tW, const float4* __restrict__ tB) {
    int z = blockIdx.z;
    const int* tok = z ? tgt : src;
    const float* emb = z ? t_emb : s_emb;
    const float4* W4 = z ? tW : sW;
    const float4* b4 = z ? tB : sB;
    bf16* XH = (z ? g_XtH : g_XsH);
    bf16* XL = (z ? g_XtL : g_XsL);
    int t = blockIdx.y;
    int w = threadIdx.x >> 5, lane = threadIdx.x & 31;
    int n4 = blockIdx.x * 8 + w;
    const float* ar = emb + (long)tok[lane*Tt + t] * Ee;
    float4 acc = b4[n4];
    #pragma unroll 4
    for (int k = 0; k < Ee; k++) {
        float a = ar[k];
        float4 wv = W4[k*(Hh/4) + n4];
        acc.x += a*wv.x; acc.y += a*wv.y; acc.z += a*wv.z; acc.w += a*wv.w;
    }
    bf16* xh = XH + (long)t*XTC;
    bf16* xl = XL + (long)t*XTC;
    stX(xh, xl, lane, n4*4+0, acc.x);
    stX(xh, xl, lane, n4*4+1, acc.y);
    stX(xh, xl, lane, n4*4+2, acc.z);
    stX(xh, xl, lane, n4*4+3, acc.w);
}

// ---------------- HMMA staged GEMM (R13 layout, splittable) ----------------
struct Pipe { uint32_t ph; unsigned base; int iss; };

__device__ void stage_part(Pipe& P, float (&acc)[2][2][4], char* sm, uint32_t smb,
    const char* Ah, const char* Al,
    const char* B1h, const char* B1l, const char* B2h, const char* B2l,
    int nch1, int c0, int c1, int nch_all)
{
    int tid = threadIdx.x, lane = tid & 31, wid = tid >> 5;
    int wm = wid >> 2, wn = (wid >> 1) & 1, wk = wid & 1;
    uint32_t aoff = (uint32_t)((lane & 15)*144 + ((lane >> 4) << 4));
    uint32_t boff = (uint32_t)((((lane >> 4) << 3) + (lane & 7))*144 + (((lane >> 3) & 1) << 4));
    for (int it = c0; it < c1; it++) {
        if (tid == 0) {
            for (; P.iss < nch_all && P.iss <= it + 3; P.iss++) {
                int sl = (int)((P.base + P.iss) & 3);
                uint32_t fb = smb + MBF_OFF + sl*8;
                mb_expect(fb, SLOT_SZ);
                uint32_t d = smb + sl*SLOT_SZ;
                bulk_g2s(d,          Ah + (long)P.iss*ACHB, ACHB, fb);
                bulk_g2s(d + ACHB,   Al + (long)P.iss*ACHB, ACHB, fb);
                const char* bh = (P.iss < nch1) ? B1h + (long)P.iss*BCHB : B2h + (long)(P.iss-nch1)*BCHB;
                const char* bl = (P.iss < nch1) ? B1l + (long)P.iss*BCHB : B2l + (long)(P.iss-nch1)*BCHB;
                bulk_g2s(d + 2*ACHB,        bh, BCHB, fb);
                bulk_g2s(d + 2*ACHB + BCHB, bl, BCHB, fb);
            }
        }
        int sl = (int)((P.base + it) & 3);
        mb_wait(smb + MBF_OFF + sl*8, (P.ph >> sl) & 1);
        P.ph ^= 1u << sl;
        uint32_t d = smb + sl*SLOT_SZ;
        uint32_t dAh = d, dAl = d + ACHB, dBh = d + 2*ACHB, dBl = d + 2*ACHB + BCHB;
        #pragma unroll
        for (int ks = 0; ks < 2; ks++) {
            uint32_t kadd = (uint32_t)((wk*32 + ks*16) << 1);
            uint32_t bh4[4], bl4[4];
            uint32_t bbase = (uint32_t)(wn*16*144) + kadd + boff;
            ldsm4(bh4, dBh + bbase);
            ldsm4(bl4, dBl + bbase);
            #pragma unroll
            for (int mt = 0; mt < 2; mt++) {
                uint32_t abase = (uint32_t)((wm*32 + mt*16)*144) + kadd + aoff;
                uint32_t a4[4], a4l[4];
                ldsm4(a4,  dAh + abase);
                ldsm4(a4l, dAl + abase);
                hmma(acc[mt][0], a4,  bh4);
                hmma(acc[mt][0], a4l, bh4);
                hmma(acc[mt][0], a4,  bl4);
                hmma(acc[mt][1], a4,  bh4 + 2);
                hmma(acc[mt][1], a4l, bh4 + 2);
                hmma(acc[mt][1], a4,  bl4 + 2);
            }
        }
        __syncthreads();
    }
}

__device__ void stage_fin(Pipe& P, float (&acc)[2][2][4], float* red, int nch_all) {
    int tid = threadIdx.x, lane = tid & 31, wid = tid >> 5;
    int wm = wid >> 2, wn = (wid >> 1) & 1, wk = wid & 1;
    int gr = lane >> 2, tig = lane & 3;
    P.base += nch_all;
    float* rw = red + wk*4224;
    #pragma unroll
    for (int mt = 0; mt < 2; mt++)
        #pragma unroll
        for (int nt = 0; nt < 2; nt++) {
            int r0 = wm*32 + mt*16 + gr;
            int cb = wn*16 + nt*8 + tig*2;
            rw[r0*33 + cb]     = acc[mt][nt][0];
            rw[r0*33 + cb + 1] = acc[mt][nt][1];
            rw[(r0+8)*33 + cb]     = acc[mt][nt][2];
            rw[(r0+8)*33 + cb + 1] = acc[mt][nt][3];
        }
    __syncthreads();
}

__device__ void stage_mma(Pipe& P, char* sm, uint32_t smb,
    const char* Ah, const char* Al,
    const char* B1h, const char* B1l, const char* B2h, const char* B2l,
    int nch1, int nch, float* red)
{
    float acc[2][2][4] = {};
    P.iss = 0;
    stage_part(P, acc, sm, smb, Ah, Al, B1h, B1l, B2h, B2l, nch1, 0, nch, nch);
    stage_fin(P, acc, red, nch);
}

__device__ void lstm_fin(const float* red, int ct, const float* __restrict__ bias,
                         const float* __restrict__ zx, float* __restrict__ c,
                         float* __restrict__ hlin, bf16* XH, bf16* XL) {
    for (int i = threadIdx.x; i < 1024; i += NTHR) {
        int nl = i >> 5, b = i & 31;
        int col = ct*128 + nl*4;
        const float* r0 = red + (nl*4)*33 + b;
        const float* r1 = r0 + 4224;
        float zi = r0[0]  + r1[0]  + bias[col];
        float zj = r0[33] + r1[33] + bias[col+1];
        float zf = r0[66] + r1[66] + bias[col+2];
        float zo = r0[99] + r1[99] + bias[col+3];
        if (zx) {
            const float* z = zx + (long)col*32 + b;
            zi += z[0]; zj += z[32]; zf += z[64]; zo += z[96];
        }
        int idx = (ct*32 + nl)*32 + b;
        float cn = c[idx]*sigf(zf + 1.f) + sigf(zi)*tanhf(zj);
        c[idx] = cn;
        float h = tanhf(cn)*sigf(zo);
        if (hlin) hlin[idx] = h;
        stX(XH, XL, b, ct*32 + nl, h);
    }
    __syncthreads();
}

// LSTM fin from two global split-K partials [cl][b] (4096 each)
__device__ void lstm_finP(const float* p0, const float* p1, int ct,
                          const float* __restrict__ bias, float* __restrict__ c,
                          float* __restrict__ hlin, bf16* XH, bf16* XL) {
    for (int i = threadIdx.x; i < 1024; i += NTHR) {
        int nl = i >> 5, b = i & 31;
        int col = ct*128 + nl*4;
        const float* q0 = p0 + (nl*4)*32 + b;
        const float* q1 = p1 + (nl*4)*32 + b;
        float zi = q0[0]  + q1[0]  + bias[col];
        float zj = q0[32] + q1[32] + bias[col+1];
        float zf = q0[64] + q1[64] + bias[col+2];
        float zo = q0[96] + q1[96] + bias[col+3];
        int idx = (ct*32 + nl)*32 + b;
        float cn = c[idx]*sigf(zf + 1.f) + sigf(zi)*tanhf(zj);
        c[idx] = cn;
        float h = tanhf(cn)*sigf(zo);
        if (hlin) hlin[idx] = h;
        stX(XH, XL, b, ct*32 + nl, h);
    }
    __syncthreads();
}

// ---------------- xgate (HMMA) ----------------
__global__ void __launch_bounds__(NTHR) xgate_mma() {
    extern __shared__ __align__(16) char dynsmem[];
    uint32_t smb = s2u(dynsmem);
    float* red = (float*)(dynsmem + RED_OFF);
    if (threadIdx.x == 0) {
        #pragma unroll
        for (int j = 0; j < 4; j++) mb_init(smb + MBF_OFF + j*8, 1);
        asm volatile("fence.proxy.async.shared::cta;" ::: "memory");
    }
    __syncthreads();
    Pipe P{0,0,0};
    int ct = blockIdx.x, t = blockIdx.y, z = blockIdx.z;
    const char* Ah = (const char*)((z ? g_AxdH : g_AxeH) + (long)ct*16*ACH);
    const char* Al = (const char*)((z ? g_AxdL : g_AxeL) + (long)ct*16*ACH);
    const char* Bh = (const char*)((z ? g_XtH : g_XsH) + (long)t*XTC);
    const char* Bl = (const char*)((z ? g_XtL : g_XsL) + (long)t*XTC);
    stage_mma(P, dynsmem, smb, Ah, Al, Bh, Bl, Bh, Bl, 16, 16, red);
    float* out = (z ? g_zxd : g_zxe) + (long)t*G4B;
    for (int i = threadIdx.x; i < 4096; i += NTHR) {
        int cl = i >> 5, b = i & 31;
        out[(long)(ct*128 + cl)*32 + b] = red[cl*33 + b] + red[4224 + cl*33 + b];
    }
}

// ---------------- grid barrier ----------------
__device__ __forceinline__ void gbar(unsigned &tgt) {
    tgt += NBLK;
    __syncthreads();
    if (threadIdx.x == 0) {
        __threadfence();
        atomicAdd(&g_bar, 1u);
        unsigned v;
        do {
            asm volatile("ld.acquire.gpu.u32 %0,[%1];" : "=r"(v) : "l"(&g_bar) : "memory");
        } while (v < tgt);
    }
    __syncthreads();
}

// ---------------- persistent sequence kernel ----------------
__global__ void __launch_bounds__(NTHR,1) seq_kernel(const float* __restrict__ b_c,
                                                     const float* __restrict__ proj_b) {
    extern __shared__ __align__(16) char dynsmem[];
    uint32_t smb = s2u(dynsmem);
    float* red = (float*)(dynsmem + RED_OFF);
    float* attw = (float*)(dynsmem + ATT_OFF);
    int tid = threadIdx.x, lane = tid & 31, wid = tid >> 5, bid = blockIdx.x;
    unsigned tgt = 0;
    if (tid == 0) {
        #pragma unroll
        for (int j = 0; j < 4; j++) mb_init(smb + MBF_OFF + j*8, 1);
        asm volatile("fence.proxy.async.shared::cta;" ::: "memory");
    }
    __syncthreads();
    Pipe P{0,0,0};
    const char* zX = (const char*)g_zeroX;

    // ---- phase 1: E0(t)[0-31] || D0(t)[32-63] || E1(t-1) split-K [64-127]
    //      + fin slot: E1 reduce+cell on [64-95]; S1(0) at it==Tt on [32-63].
    for (int it = 0; it <= Tt; it++) {
        if (bid < 32 && it < Tt) {
            int t = it, ct = bid;
            const char* bh = t ? (const char*)(g_h0eH + (long)((t-1)&1)*XTC) : zX;
            const char* bl = t ? (const char*)(g_h0eL + (long)((t-1)&1)*XTC) : zX;
            stage_mma(P, dynsmem, smb,
                      (const char*)(g_Ae0H + (long)ct*16*ACH), (const char*)(g_Ae0L + (long)ct*16*ACH),
                      bh, bl, bh, bl, 16, 16, red);
            lstm_fin(red, ct, g_bre, g_zxe + (long)t*G4B, g_c0e, nullptr,
                     g_h0eH + (long)(t&1)*XTC, g_h0eL + (long)(t&1)*XTC);
        } else if (bid >= 32 && bid < 64 && it < Tt) {
            int t = it, ct = bid - 32;
            const char* bh = t ? (const char*)(g_txH + (long)(t-1)*XTC) : zX;
            const char* bl = t ? (const char*)(g_txL + (long)(t-1)*XTC) : zX;
            stage_mma(P, dynsmem, smb,
                      (const char*)(g_Ad0H + (long)ct*16*ACH), (const char*)(g_Ad0L + (long)ct*16*ACH),
                      bh, bl, bh, bl, 16, 16, red);
            lstm_fin(red, ct, g_brd, g_zxd + (long)t*G4B, g_c0d, nullptr,
                     g_txH + (long)t*XTC, g_txL + (long)t*XTC);
        } else if (bid >= 32 && bid < 64 && it == Tt) {
            // S1(0): dec layer1, t=0 (h1prev = 0)
            int ct = bid - 32;
            stage_mma(P, dynsmem, smb,
                      (const char*)(g_Ad1H + (long)ct*32*ACH), (const char*)(g_Ad1L + (long)ct*32*ACH),
                      (const char*)g_txH, (const char*)g_txL, zX, zX, 16, 32, red);
            lstm_fin(red, ct, g_brd + G4, nullptr, g_c1d, g_h1d,
                     g_h1SH, g_h1SL);
        } else if (bid >= 64 && it >= 1) {
            // E1(t-1) split-K: kq0 = h-from-l0 half, kq1 = recurrent half
            int t = it - 1, idx = bid - 64, ct = idx & 31, kq = idx >> 5;
            const char* Ah = (const char*)(g_Ae1H + (long)(ct*32 + kq*16)*ACH);
            const char* Al = (const char*)(g_Ae1L + (long)(ct*32 + kq*16)*ACH);
            const char *bh, *bl;
            if (kq == 0) {
                bh = (const char*)(g_h0eH + (long)(t&1)*XTC);
                bl = (const char*)(g_h0eL + (long)(t&1)*XTC);
            } else {
                bh = t ? (const char*)(g_encSH + (long)((t-1)&1)*XTC) : zX;
                bl = t ? (const char*)(g_encSL + (long)((t-1)&1)*XTC) : zX;
            }
            stage_mma(P, dynsmem, smb, Ah, Al, bh, bl, bh, bl, 16, 16, red);
            float* dst = g_e1P + (long)(kq*32 + ct)*4096;
            for (int i = tid; i < 4096; i += NTHR) {
                int cl = i >> 5, b = i & 31;
                dst[cl*32 + b] = red[cl*33 + b] + red[4224 + cl*33 + b];
            }
            __syncthreads();
        }
        gbar(tgt);
        if (bid >= 64 && bid < 96 && it >= 1) {
            int t = it - 1, ct = bid - 64;
            lstm_finP(g_e1P + (long)ct*4096, g_e1P + (long)(32 + ct)*4096, ct,
                      g_bre + G4, g_c1e, g_encHs + (long)t*HB,
                      g_encSH + (long)(t&1)*XTC, g_encSL + (long)(t&1)*XTC);
        }
        gbar(tgt);
    }

    // ---- phase 2: S1(t+1) overlapped on [96-127]; oe-reduce(t-1) on [80-95] in slotA
    float s1acc[2][2][4];
    for (int t = 0; t < Tt; t++) {
        int p = t & 1;
        float* h1cur = g_h1d + p*HB;
        int tn = t + 1, pn = tn & 1;
        bool doS1 = (t < Tt - 1);
        const char* s1Ah = (const char*)(g_Ad1H + (long)(bid-96)*32*ACH);
        const char* s1Al = (const char*)(g_Ad1L + (long)(bid-96)*32*ACH);
        const char* s1B1h = (const char*)(g_txH + (long)tn*XTC);
        const char* s1B1l = (const char*)(g_txL + (long)tn*XTC);
        const char* s1B2h = (const char*)(g_h1SH + (long)p*XTC);
        const char* s1B2l = (const char*)(g_h1SL + (long)p*XTC);

        // slotA: scores [0-63] || W_c h-half [64-79] || oe-reduce(t-1) [80-95] || S1p1 [96-127]
        if (bid < Tt) {
            const float* e = g_encHs + (long)bid*HB;
            float s = 0.f;
            #pragma unroll 4
            for (int hh = wid*64; hh < wid*64 + 64; hh++)
                s += h1cur[hh*Bb + lane] * e[hh*Bb + lane];
            attw[wid*33 + lane] = s;
            __syncthreads();
            if (wid == 0) {
                float a = 0.f;
                #pragma unroll
                for (int j = 0; j < 16; j++) a += attw[j*33 + lane];
                g_scoresT[bid*Bb + lane] = a;
            }
            __syncthreads();
        } else if (bid < 80) {
            int idx = bid - 64, ct = idx >> 1, kq = idx & 1;
            stage_mma(P, dynsmem, smb,
                      (const char*)(g_AwcH + (long)(ct*32 + kq*8)*ACH),
                      (const char*)(g_AwcL + (long)(ct*32 + kq*8)*ACH),
                      (const char*)(g_h1SH + (long)p*XTC + (long)kq*8*BCH),
                      (const char*)(g_h1SL + (long)p*XTC + (long)kq*8*BCH),
                      (const char*)g_ctxH, (const char*)g_ctxL, 8, 8, red);
            for (int i = tid; i < 4096; i += NTHR) {
                int cl = i >> 5, b = i & 31;
                g_wcP[(long)kq*HB + (ct*128 + cl)*32 + b] =
                    red[cl*33 + b] + red[4224 + cl*33 + b];
            }
            __syncthreads();
        } else if (bid < 96) {
            if (t > 0) {
                int tr = t - 1;
                for (int i = tid; i < 1024; i += NTHR) {
                    int cl = i >> 5, b = i & 31;
                    int col = (bid - 80)*32 + cl;
                    float v = proj_b[col];
                    #pragma unroll
                    for (int s4 = 0; s4 < 4; s4++) v += g_oeP[(long)s4*(Ee*Bb) + col*32 + b];
                    splitw(v, g_oeH, g_oeL, (long)(tr*32 + b)*Ee + col);
                }
                __syncthreads();
            }
        } else if (doS1) {
            #pragma unroll
            for (int a1 = 0; a1 < 2; a1++)
                #pragma unroll
                for (int a2 = 0; a2 < 2; a2++)
                    #pragma unroll
                    for (int a3 = 0; a3 < 4; a3++) s1acc[a1][a2][a3] = 0.f;
            P.iss = 0;
            stage_part(P, s1acc, dynsmem, smb, s1Ah, s1Al,
                       s1B1h, s1B1l, s1B2h, s1B2l, 16, 0, 8, 32);
        }
        gbar(tgt);

        // slotB: softmax + ctx [0-63] || S1p2 [96-127]
        if (bid < 64) {
            if (wid == 0) {
                float mx = -1e30f;
                #pragma unroll
                for (int q = 0; q < Tt; q++) mx = fmaxf(mx, g_scoresT[q*Bb + lane]);
                float sum = 0.f;
                #pragma unroll
                for (int q = 0; q < Tt; q++) {
                    float e = expf(g_scoresT[q*Bb + lane] - mx);
                    attw[q*33 + lane] = e; sum += e;
                }
                float inv = 1.f/sum;
                #pragma unroll
                for (int q = 0; q < Tt; q++) attw[q*33 + lane] *= inv;
            }
            __syncthreads();
            int hh = bid*16 + wid;
            float s = 0.f;
            #pragma unroll 8
            for (int q = 0; q < Tt; q++)
                s += attw[q*33 + lane] * g_encHs[((long)q*Hh + hh)*Bb + lane];
            stX(g_ctxH, g_ctxL, lane, hh, s);
        } else if (bid >= 96 && doS1) {
            stage_part(P, s1acc, dynsmem, smb, s1Ah, s1Al,
                       s1B1h, s1B1l, s1B2h, s1B2l, 16, 8, 16, 32);
        }
        gbar(tgt);

        // slotC: W_c ctx-half [0-15] || S1p3 [96-127]
        if (bid < 16) {
            int ct = bid >> 1, kq = bid & 1;
            stage_mma(P, dynsmem, smb,
                      (const char*)(g_AwcH + (long)(ct*32 + 16 + kq*8)*ACH),
                      (const char*)(g_AwcL + (long)(ct*32 + 16 + kq*8)*ACH),
                      (const char*)(g_ctxH + (long)kq*8*BCH),
                      (const char*)(g_ctxL + (long)kq*8*BCH),
                      (const char*)g_ctxH, (const char*)g_ctxL, 8, 8, red);
            for (int i = tid; i < 4096; i += NTHR) {
                int cl = i >> 5, b = i & 31;
                g_wcP[(long)(2 + kq)*HB + (ct*128 + cl)*32 + b] =
                    red[cl*33 + b] + red[4224 + cl*33 + b];
            }
            __syncthreads();
        } else if (bid >= 96 && doS1) {
            stage_part(P, s1acc, dynsmem, smb, s1Ah, s1Al,
                       s1B1h, s1B1l, s1B2h, s1B2l, 16, 16, 24, 32);
        }
        gbar(tgt);

        // slotD: reduce -> ht [0-7] || S1p4 + finish [96-127]
        if (bid < 8) {
            for (int i = tid; i < 4096; i += NTHR) {
                int cl = i >> 5, b = i & 31;
                int col = bid*128 + cl;
                float v = b_c[col];
                #pragma unroll
                for (int s4 = 0; s4 < 4; s4++) v += g_wcP[(long)s4*HB + col*32 + b];
                stX(g_htH, g_htL, b, col, v);
            }
            __syncthreads();
        } else if (bid >= 96 && doS1) {
            stage_part(P, s1acc, dynsmem, smb, s1Ah, s1Al,
                       s1B1h, s1B1l, s1B2h, s1B2l, 16, 24, 32, 32);
            stage_fin(P, s1acc, red, 32);
            lstm_fin(red, bid - 96, g_brd + G4, nullptr, g_c1d, g_h1d + (long)pn*HB,
                     g_h1SH + (long)pn*XTC, g_h1SL + (long)pn*XTC);
        }
        gbar(tgt);

        // slotE: proj split-K [0-15]
        if (bid < 16) {
            int ct = bid >> 2, kq = bid & 3;
            stage_mma(P, dynsmem, smb,
                      (const char*)(g_ApjH + (long)(ct*16 + kq*4)*ACH),
                      (const char*)(g_ApjL + (long)(ct*16 + kq*4)*ACH),
                      (const char*)(g_htH + (long)kq*4*BCH),
                      (const char*)(g_htL + (long)kq*4*BCH),
                      (const char*)g_htH, (const char*)g_htL, 4, 4, red);
            for (int i = tid; i < 4096; i += NTHR) {
                int cl = i >> 5, b = i & 31;
                g_oeP[(long)kq*(Ee*Bb) + (ct*128 + cl)*32 + b] =
                    red[cl*33 + b] + red[4224 + cl*33 + b];
            }
            __syncthreads();
        }
        gbar(tgt);
        // (oe-reduce for this t happens in next step's slotA / post-loop)
    }

    // final oe reduce for t = Tt-1 (after last gbar; kernel-exit orders vs next launch)
    if (bid >= 80 && bid < 96) {
        int tr = Tt - 1;
        for (int i = tid; i < 1024; i += NTHR) {
            int cl = i >> 5, b = i & 31;
            int col = (bid - 80)*32 + cl;
            float v = proj_b[col];
            #pragma unroll
            for (int s4 = 0; s4 < 4; s4++) v += g_oeP[(long)s4*(Ee*Bb) + col*32 + b];
            splitw(v, g_oeH, g_oeL, (long)(tr*32 + b)*Ee + col);
        }
    }
}

// ---------------- HMMA vocab GEMM + exp epilogue (ldmatrix) ----------------
#define LP 40
__global__ void __launch_bounds__(512) logits_hmma(const float* __restrict__ bias,
                                                   float* __restrict__ E) {
    __shared__ bf16 Ah[128*LP], Al[128*LP], Bh[128*LP], Bl[128*LP];
    int tid = threadIdx.x, lane = tid & 31, wid = tid >> 5;
    int gr = lane >> 2, tig = lane & 3;
    int wm = wid >> 2, wn = wid & 3;
    int bn = blockIdx.x*128, bm = blockIdx.y*128;
    int r = tid & 127, seg = tid >> 7;
    uint32_t sAh = s2u(Ah), sAl = s2u(Al), sBh = s2u(Bh), sBl = s2u(Bl);
    uint32_t aoff = (uint32_t)((lane & 15)*(LP*2) + ((lane >> 4) << 4));
    uint32_t boff = (uint32_t)((((lane >> 4) << 3) + (lane & 7))*(LP*2) + (((lane >> 3) & 1) << 4));
    float acc[2][4][4] = {};
    for (int k0 = 0; k0 < 512; k0 += 32) {
        *(uint4*)&Ah[r*LP + seg*8] = *(const uint4*)&g_oeH[(long)(bm+r)*Ee + k0 + seg*8];
        *(uint4*)&Al[r*LP + seg*8] = *(const uint4*)&g_oeL[(long)(bm+r)*Ee + k0 + seg*8];
        *(uint4*)&Bh[r*LP + seg*8] = *(const uint4*)&g_WoTH[(long)(bn+r)*Ee + k0 + seg*8];
        *(uint4*)&Bl[r*LP + seg*8] = *(const uint4*)&g_WoTL[(long)(bn+r)*Ee + k0 + seg*8];
        __syncthreads();
        #pragma unroll
        for (int ks = 0; ks < 2; ks++) {
            uint32_t kadd = (uint32_t)(ks << 5);
            uint32_t bh4[2][4], bl4[2][4];
            #pragma unroll
            for (int nfp = 0; nfp < 2; nfp++) {
                uint32_t bb = (uint32_t)((wn*32 + nfp*16)*(LP*2)) + kadd + boff;
                ldsm4(bh4[nfp], sBh + bb);
                ldsm4(bl4[nfp], sBl + bb);
            }
            #pragma unroll
            for (int mt = 0; mt < 2; mt++) {
                uint32_t ab = (uint32_t)((wm*32 + mt*16)*(LP*2)) + kadd + aoff;
                uint32_t a4[4], a4l[4];
                ldsm4(a4,  sAh + ab);
                ldsm4(a4l, sAl + ab);
                #pragma unroll
                for (int nfp = 0; nfp < 2; nfp++) {
                    hmma(acc[mt][nfp*2],   a4,  bh4[nfp]);
                    hmma(acc[mt][nfp*2],   a4l, bh4[nfp]);
                    hmma(acc[mt][nfp*2],   a4,  bl4[nfp]);
                    hmma(acc[mt][nfp*2+1], a4,  bh4[nfp] + 2);
                    hmma(acc[mt][nfp*2+1], a4l, bh4[nfp] + 2);
                    hmma(acc[mt][nfp*2+1], a4,  bl4[nfp] + 2);
                }
            }
        }
        __syncthreads();
    }
    #pragma unroll
    for (int mt = 0; mt < 2; mt++)
        #pragma unroll
        for (int nf = 0; nf < 4; nf++) {
            int row = bm + wm*32 + mt*16 + gr;
            int col = bn + wn*32 + nf*8 + tig*2;
            float b0 = bias[col], b1 = bias[col+1];
            float* e0 = E + (size_t)row*VTv + col;
            e0[0] = expf(acc[mt][nf][0] + b0);
            e0[1] = expf(acc[mt][nf][1] + b1);
            float* e1 = E + (size_t)(row+8)*VTv + col;
            e1[0] = expf(acc[mt][nf][2] + b0);
            e1[1] = expf(acc[mt][nf][3] + b1);
        }
}

__global__ void softmax_norm(const float* __restrict__ E, float* __restrict__ out) {
    int m = blockIdx.x;
    const float* er = E + (size_t)m*VTv;
    int tid = threadIdx.x;
    __shared__ float red[256];
    float sum = 0.f;
    for (int i = tid; i < VTv; i += 256) sum += er[i];
    red[tid] = sum; __syncthreads();
    for (int s = 128; s; s >>= 1) { if (tid < s) red[tid] += red[tid+s]; __syncthreads(); }
    float inv = 1.f/red[0];
    int t = m >> 5, b = m & 31;
    float* orow = out + (size_t)(b*Tt + t)*VTv;
    for (int i = tid; i < VTv; i += 256) orow[i] = er[i]*inv;
}

// ---------------- host ----------------
extern "C" void kernel_launch(void* const* d_in, const int* in_sizes, int n_in,
                              void* d_out, int out_size) {
    const int*   src    = (const int*)d_in[0];
    const int*   tgt    = (const int*)d_in[1];
    const float* s_emb  = (const float*)d_in[2];
    const float* s_pW   = (const float*)d_in[3];
    const float* s_pb   = (const float*)d_in[4];
    const float* t_emb  = (const float*)d_in[5];
    const float* t_pW   = (const float*)d_in[6];
    const float* t_pb   = (const float*)d_in[7];
    const float* enc_W  = (const float*)d_in[8];
    const float* enc_b  = (const float*)d_in[9];
    const float* dec_W  = (const float*)d_in[10];
    const float* dec_b  = (const float*)d_in[11];
    const float* W_c    = (const float*)d_in[12];
    const float* b_c    = (const float*)d_in[13];
    const float* proj_W = (const float*)d_in[14];
    const float* proj_b = (const float*)d_in[15];
    const float* proj_Wo= (const float*)d_in[16];
    const float* proj_bo= (const float*)d_in[17];
    float* out = (float*)d_out;

    float* elog;
    cudaGetSymbolAddress((void**)&elog, g_elog);

    cudaFuncSetAttribute(seq_kernel, cudaFuncAttributeMaxDynamicSharedMemorySize, SMEM_SEQ);
    cudaFuncSetAttribute(xgate_mma,  cudaFuncAttributeMaxDynamicSharedMemorySize, SMEM_SEQ);

    prep<<<dim3(4096,4), 256>>>(enc_W, enc_b, dec_W, dec_b, W_c, proj_W);
    transWo<<<dim3(1000,16), dim3(32,8)>>>(proj_Wo);
    embed2<<<dim3(32,64,2), 256>>>(src, tgt, s_emb, t_emb,
                                   (const float4*)s_pW, (const float4*)s_pb,
                                   (const float4*)t_pW, (const float4*)t_pb);
    xgate_mma<<<dim3(32,64,2), NTHR, SMEM_SEQ>>>();
    seq_kernel<<<NBLK, NTHR, SMEM_SEQ>>>(b_c, proj_b);
    logits_hmma<<<dim3(VTv/128, 2048/128), 512>>>(proj_bo, elog);
    softmax_norm<<<Tt*Bb, 256>>>(elog, out);
}